// round 1
// baseline (speedup 1.0000x reference)
#include <cuda_runtime.h>
#include <cstdint>

// Problem constants
#define BATCH   512
#define SEQ     64
#define CH      512
#define HEADS   16
#define HDIM    32
#define GRIDN   5
#define MROWS   (BATCH * SEQ)          // 32768
#define KAUG    (CH * GRIDN)           // 2560
#define XAW     (CH + KAUG)            // 3072

// Scratch (device globals — no allocation allowed)
__device__ float g_XA[(size_t)MROWS * XAW];    // [M, 3072]: swish | phi
__device__ float g_Q[(size_t)MROWS * CH];
__device__ float g_K[(size_t)MROWS * CH];
__device__ float g_V[(size_t)MROWS * CH];
__device__ float g_CTX[(size_t)MROWS * CH];

// ---------------------------------------------------------------------------
// Prep: XA[m, 0:512] = swish(x), XA[m, 512 + c*5 + g] = exp(-(x - grid[g])^2)
// grid = {-2,-1,0,1,2}, h = 1
// ---------------------------------------------------------------------------
__global__ __launch_bounds__(256) void prep_kernel(const float* __restrict__ x,
                                                   float* __restrict__ XA) {
    int idx = blockIdx.x * blockDim.x + threadIdx.x;   // m*512 + c
    if (idx >= MROWS * CH) return;
    int m = idx >> 9;
    int c = idx & 511;
    float v = x[idx];
    float sig = 1.0f / (1.0f + __expf(-v));
    float* row = XA + (size_t)m * XAW;
    row[c] = v * sig;
    float* ph = row + CH + c * GRIDN;
#pragma unroll
    for (int g = 0; g < GRIDN; g++) {
        float d = v - (float)(g - 2);
        ph[g] = __expf(-d * d);
    }
}

// ---------------------------------------------------------------------------
// SGEMM: C[M,N] = A[M,K] @ B[K,N] (+C if accumulate) (+bias[n] if bias)
// BM=BN=128, BK=8, 256 threads, 8x8 per thread.
// Requires M%128==0, N%128==0, K%8==0, pointers 16B-aligned, lda/ldb/ldc%4==0.
// ---------------------------------------------------------------------------
#define BM 128
#define BN 128
#define BK 8
#define TM 8
#define TN 8

__global__ __launch_bounds__(256) void sgemm_kernel(
    const float* __restrict__ A, int lda,
    const float* __restrict__ B, int ldb,
    float* __restrict__ C, int ldc,
    int K, const float* __restrict__ bias, int accumulate)
{
    __shared__ float As[BK][BM];
    __shared__ float Bs[BK][BN];

    int tid = threadIdx.x;
    int bm = blockIdx.y * BM;
    int bn = blockIdx.x * BN;

    int tx = tid & 15;          // 0..15 (col group)
    int ty = tid >> 4;          // 0..15 (row group)

    int a_row = tid >> 1;       // 0..127
    int a_col = (tid & 1) * 4;  // 0 or 4
    int b_row = tid >> 5;       // 0..7
    int b_col = (tid & 31) * 4; // 0..124

    float acc[TM][TN];
#pragma unroll
    for (int i = 0; i < TM; i++)
#pragma unroll
        for (int j = 0; j < TN; j++) acc[i][j] = 0.0f;

    const float* Aptr = A + (size_t)bm * lda;
    const float* Bptr = B + bn;

    for (int k0 = 0; k0 < K; k0 += BK) {
        float4 av = *(const float4*)(Aptr + (size_t)a_row * lda + k0 + a_col);
        As[a_col + 0][a_row] = av.x;
        As[a_col + 1][a_row] = av.y;
        As[a_col + 2][a_row] = av.z;
        As[a_col + 3][a_row] = av.w;
        float4 bv = *(const float4*)(Bptr + (size_t)(k0 + b_row) * ldb + b_col);
        *(float4*)&Bs[b_row][b_col] = bv;
        __syncthreads();
#pragma unroll
        for (int k = 0; k < BK; k++) {
            float ar[TM], br[TN];
#pragma unroll
            for (int i = 0; i < TM; i += 4)
                *(float4*)&ar[i] = *(const float4*)&As[k][ty * TM + i];
#pragma unroll
            for (int j = 0; j < TN; j += 4)
                *(float4*)&br[j] = *(const float4*)&Bs[k][tx * TN + j];
#pragma unroll
            for (int i = 0; i < TM; i++)
#pragma unroll
                for (int j = 0; j < TN; j++)
                    acc[i][j] = fmaf(ar[i], br[j], acc[i][j]);
        }
        __syncthreads();
    }

#pragma unroll
    for (int i = 0; i < TM; i++) {
        int row = bm + ty * TM + i;
        float* Crow = C + (size_t)row * ldc + bn;
#pragma unroll
        for (int j = 0; j < TN; j += 4) {
            int col = tx * TN + j;
            float4 r = make_float4(acc[i][j], acc[i][j + 1], acc[i][j + 2], acc[i][j + 3]);
            if (accumulate) {
                float4 o = *(float4*)(Crow + col);
                r.x += o.x; r.y += o.y; r.z += o.z; r.w += o.w;
            }
            if (bias) {
                r.x += bias[bn + col + 0];
                r.y += bias[bn + col + 1];
                r.z += bias[bn + col + 2];
                r.w += bias[bn + col + 3];
            }
            *(float4*)(Crow + col) = r;
        }
    }
}

// ---------------------------------------------------------------------------
// Attention: one block per (b, h). N=64, hd=32.
// scores = Q@K^T * scale + bias(rel_idx); softmax; ctx = attn @ V
// ---------------------------------------------------------------------------
__global__ __launch_bounds__(256) void attn_kernel(
    const float* __restrict__ Q, const float* __restrict__ K,
    const float* __restrict__ V, const float* __restrict__ bias_table,
    float* __restrict__ CTX)
{
    __shared__ float qs[SEQ][HDIM];
    __shared__ float ks[SEQ][HDIM];
    __shared__ float vs[SEQ][HDIM];
    __shared__ float sc[SEQ][SEQ];

    int tid = threadIdx.x;
    int b = blockIdx.x >> 4;
    int h = blockIdx.x & 15;

    const size_t base = (size_t)b * SEQ * CH + h * HDIM;
    const float* Qb = Q + base;
    const float* Kb = K + base;
    const float* Vb = V + base;

    // load 64x32 tiles (512 float4 each, 2 per thread)
#pragma unroll
    for (int i = tid; i < SEQ * HDIM / 4; i += 256) {
        int n = i >> 3;       // row
        int d4 = i & 7;       // float4 within row
        size_t goff = (size_t)n * CH + d4 * 4;
        ((float4*)&qs[0][0])[i] = *(const float4*)(Qb + goff);
        ((float4*)&ks[0][0])[i] = *(const float4*)(Kb + goff);
        ((float4*)&vs[0][0])[i] = *(const float4*)(Vb + goff);
    }
    __syncthreads();

    const float scale = 0.17677669529663687f;  // 1/sqrt(32)

    // scores: thread -> row n = tid>>2, m range = (tid&3)*16
    {
        int n = tid >> 2;
        int m0 = (tid & 3) * 16;
        int i1 = n >> 3, j1 = n & 7;
#pragma unroll 4
        for (int m = m0; m < m0 + 16; m++) {
            float s = 0.0f;
#pragma unroll
            for (int d = 0; d < HDIM; d++) s = fmaf(qs[n][d], ks[m][d], s);
            int i2 = m >> 3, j2 = m & 7;
            int ridx = (i1 - i2 + 7) * 15 + (j1 - j2 + 7);
            sc[n][m] = s * scale + bias_table[ridx * HEADS + h];
        }
    }
    __syncthreads();

    // softmax per row (threads 0..63)
    if (tid < SEQ) {
        int n = tid;
        float mx = -1e30f;
#pragma unroll 8
        for (int m = 0; m < SEQ; m++) mx = fmaxf(mx, sc[n][m]);
        float sum = 0.0f;
#pragma unroll 8
        for (int m = 0; m < SEQ; m++) {
            float e = __expf(sc[n][m] - mx);
            sc[n][m] = e;
            sum += e;
        }
        float inv = 1.0f / sum;
#pragma unroll 8
        for (int m = 0; m < SEQ; m++) sc[n][m] *= inv;
    }
    __syncthreads();

    // ctx: thread -> row n = tid>>2, d block = (tid&3)*8
    {
        int n = tid >> 2;
        int d0 = (tid & 3) * 8;
        float accv[8];
#pragma unroll
        for (int j = 0; j < 8; j++) accv[j] = 0.0f;
#pragma unroll 8
        for (int m = 0; m < SEQ; m++) {
            float a = sc[n][m];
#pragma unroll
            for (int j = 0; j < 8; j++) accv[j] = fmaf(a, vs[m][d0 + j], accv[j]);
        }
        float* out = CTX + base + (size_t)n * CH + d0;
#pragma unroll
        for (int j = 0; j < 8; j += 4)
            *(float4*)(out + j) = make_float4(accv[j], accv[j + 1], accv[j + 2], accv[j + 3]);
    }
}

// ---------------------------------------------------------------------------
// Launch
// ---------------------------------------------------------------------------
extern "C" void kernel_launch(void* const* d_in, const int* in_sizes, int n_in,
                              void* d_out, int out_size) {
    const float* x          = (const float*)d_in[0];
    const float* Wq         = (const float*)d_in[1];
    const float* Wk_base    = (const float*)d_in[2];
    const float* Wk_spline  = (const float*)d_in[3];
    const float* Wv         = (const float*)d_in[4];
    const float* Wproj      = (const float*)d_in[5];
    const float* bproj      = (const float*)d_in[6];
    const float* bias_table = (const float*)d_in[7];
    float* out = (float*)d_out;

    float *XA, *Qp, *Kp, *Vp, *CTX;
    cudaGetSymbolAddress((void**)&XA, g_XA);
    cudaGetSymbolAddress((void**)&Qp, g_Q);
    cudaGetSymbolAddress((void**)&Kp, g_K);
    cudaGetSymbolAddress((void**)&Vp, g_V);
    cudaGetSymbolAddress((void**)&CTX, g_CTX);

    prep_kernel<<<(MROWS * CH + 255) / 256, 256>>>(x, XA);

    dim3 gg(CH / BN, MROWS / BM);   // (4, 256)
    // q = x @ Wq
    sgemm_kernel<<<gg, 256>>>(x, CH, Wq, CH, Qp, CH, CH, nullptr, 0);
    // v = x @ Wv
    sgemm_kernel<<<gg, 256>>>(x, CH, Wv, CH, Vp, CH, CH, nullptr, 0);
    // k = swish(x) @ Wk_base
    sgemm_kernel<<<gg, 256>>>(XA, XAW, Wk_base, CH, Kp, CH, CH, nullptr, 0);
    // k += phi(x) @ Wk_spline
    sgemm_kernel<<<gg, 256>>>(XA + CH, XAW, Wk_spline, CH, Kp, CH, KAUG, nullptr, 1);
    // attention
    attn_kernel<<<BATCH * HEADS, 256>>>(Qp, Kp, Vp, bias_table, CTX);
    // out = ctx @ Wproj + bproj
    sgemm_kernel<<<gg, 256>>>(CTX, CH, Wproj, CH, out, CH, CH, bproj, 0);
}

// round 3
// speedup vs baseline: 2.4183x; 2.4183x over previous
#include <cuda_runtime.h>
#include <cstdint>

// Problem constants
#define BATCH   512
#define SEQ     64
#define CH      512
#define HEADS   16
#define HDIM    32
#define GRIDN   5
#define MROWS   (BATCH * SEQ)          // 32768
#define XAW     (CH * (GRIDN + 1))     // 3072: [swish | phi0 | ... | phi4]

// Scratch (device globals — no allocation allowed)
__device__ float g_XA[(size_t)MROWS * XAW];
__device__ float g_Q[(size_t)MROWS * CH];
__device__ float g_K[(size_t)MROWS * CH];
__device__ float g_V[(size_t)MROWS * CH];
__device__ float g_CTX[(size_t)MROWS * CH];
__device__ float g_WqT[CH * CH];          // [n][k]
__device__ float g_WvT[CH * CH];
__device__ float g_WpT[CH * CH];
__device__ float g_WkT[(size_t)CH * XAW]; // [n][3072]

// ---------------------------------------------------------------------------
// PTX helpers (base sm_103 feature set only: ldmatrix/mma.sync/cp.async)
// ---------------------------------------------------------------------------
__device__ __forceinline__ uint32_t smem_u32(const void* p) {
    uint32_t a;
    asm("{ .reg .u64 t; cvta.to.shared.u64 t, %1; cvt.u32.u64 %0, t; }" : "=r"(a) : "l"(p));
    return a;
}
#define CP_ASYNC16(dst, src) \
    asm volatile("cp.async.cg.shared.global [%0], [%1], 16;" :: "r"(dst), "l"(src))
#define CP_COMMIT() asm volatile("cp.async.commit_group;" ::: "memory")
#define CP_WAIT1()  asm volatile("cp.async.wait_group 1;" ::: "memory")
#define CP_WAIT0()  asm volatile("cp.async.wait_group 0;" ::: "memory")

#define LDSM4(r0, r1, r2, r3, addr) \
    asm volatile("ldmatrix.sync.aligned.m8n8.x4.shared.b16 {%0,%1,%2,%3}, [%4];" \
                 : "=r"(r0), "=r"(r1), "=r"(r2), "=r"(r3) : "r"(addr))

#define CVT_TF32(x) asm volatile("cvt.rna.tf32.f32 %0, %0;" : "+r"(x))

#define MMA_TF32(d, a, b) \
    asm volatile("mma.sync.aligned.m16n8k8.row.col.f32.tf32.tf32.f32 " \
                 "{%0,%1,%2,%3}, {%4,%5,%6,%7}, {%8,%9}, {%0,%1,%2,%3};" \
                 : "+f"((d)[0]), "+f"((d)[1]), "+f"((d)[2]), "+f"((d)[3]) \
                 : "r"((a)[0]), "r"((a)[1]), "r"((a)[2]), "r"((a)[3]), \
                   "r"((b)[0]), "r"((b)[1]))

// ---------------------------------------------------------------------------
// Prep: XA[m, c] = swish(x), XA[m, 512 + g*512 + c] = exp(-(x - (g-2))^2)
// ---------------------------------------------------------------------------
__global__ __launch_bounds__(256) void prep_kernel(const float* __restrict__ x,
                                                   float* __restrict__ XA) {
    int idx = blockIdx.x * blockDim.x + threadIdx.x;
    if (idx >= MROWS * CH) return;
    int m = idx >> 9;
    int c = idx & 511;
    float v = x[idx];
    float* row = XA + (size_t)m * XAW;
    row[c] = v / (1.0f + __expf(-v));
#pragma unroll
    for (int g = 0; g < GRIDN; g++) {
        float d = v - (float)(g - 2);
        row[CH + g * CH + c] = __expf(-d * d);
    }
}

// ---------------------------------------------------------------------------
// Weight transposes: WT[n,k] = W[k,n]
// ---------------------------------------------------------------------------
__global__ __launch_bounds__(256) void trans512_kernel(const float* __restrict__ W,
                                                       float* __restrict__ WT) {
    int idx = blockIdx.x * blockDim.x + threadIdx.x;
    if (idx >= CH * CH) return;
    int n = idx >> 9;
    int k = idx & 511;
    WT[idx] = W[k * CH + n];
}

// WkT[n][k]: k<512 -> Wk_base[k][n]; k=512+g*512+c -> Wk_spline[c*5+g][n]
__global__ __launch_bounds__(256) void build_wkt_kernel(const float* __restrict__ Wb,
                                                        const float* __restrict__ Ws,
                                                        float* __restrict__ WkT) {
    int idx = blockIdx.x * blockDim.x + threadIdx.x;
    if (idx >= CH * XAW) return;
    int n = idx / XAW;
    int k = idx - n * XAW;
    float v;
    if (k < CH) {
        v = Wb[k * CH + n];
    } else {
        int kk = k - CH;
        int g = kk >> 9;
        int c = kk & 511;
        v = Ws[(c * GRIDN + g) * CH + n];
    }
    WkT[idx] = v;
}

// ---------------------------------------------------------------------------
// tf32 mma.sync GEMM: C[M, 512] = A[M, K] @ Bt[512, K]^T (+bias)
// BM=BN=128, BK=32; 8 warps (4 x 2), warp tile 32x64; ldmatrix + cp.async x2.
// Smem per stage: A 128x32 fl (16KB) + B 128x32 fl (16KB); 2 stages = 64KB.
// XOR swizzle within 128B rows: float4 idx = row*8 + (c4 ^ (row&7)).
// ---------------------------------------------------------------------------
#define BK        32
#define STAGE_F4  2048
#define SMEM_TOT  (2 * STAGE_F4 * 16)   // 65536

__global__ __launch_bounds__(256, 2) void gemm_tf32_kernel(
    const float* __restrict__ A, int lda,
    const float* __restrict__ Bt, int K,
    float* __restrict__ C,
    const float* __restrict__ bias)
{
    extern __shared__ __align__(16) float4 sm4[];
    const uint32_t sbase = smem_u32(sm4);
    const int tid = threadIdx.x;
    const int bm = blockIdx.y * 128;
    const int bn = blockIdx.x * 128;
    const int NC = K / BK;

    const int lane = tid & 31, wid = tid >> 5;
    const int wm = (wid & 3) * 32;         // warp row offset
    const int wn = (wid >> 2) * 64;        // warp col offset
    const int mat = lane >> 3, mr = lane & 7;

    float acc[2][8][4];
#pragma unroll
    for (int mt = 0; mt < 2; mt++)
#pragma unroll
        for (int nt = 0; nt < 8; nt++)
#pragma unroll
            for (int j = 0; j < 4; j++) acc[mt][nt][j] = 0.0f;

    auto load_chunk = [&](int c, int s) {
        const float* Ak = A + (size_t)bm * lda + c * BK;
        const float* Bk = Bt + (size_t)bn * K + c * BK;
        const uint32_t aOff = sbase + s * (STAGE_F4 * 16);
        const uint32_t bOff = aOff + 1024 * 16;
#pragma unroll
        for (int i = 0; i < 4; i++) {
            int u = tid + 256 * i;
            int row = u >> 3, c4 = u & 7;
            uint32_t d = aOff + (uint32_t)(row * 8 + (c4 ^ (row & 7))) * 16;
            CP_ASYNC16(d, Ak + (size_t)row * lda + c4 * 4);
        }
#pragma unroll
        for (int i = 0; i < 4; i++) {
            int u = tid + 256 * i;
            int row = u >> 3, c4 = u & 7;
            uint32_t d = bOff + (uint32_t)(row * 8 + (c4 ^ (row & 7))) * 16;
            CP_ASYNC16(d, Bk + (size_t)row * K + c4 * 4);
        }
    };

    load_chunk(0, 0); CP_COMMIT();

    for (int c = 0; c < NC; c++) {
        const int s = c & 1;
        if (c + 1 < NC) { load_chunk(c + 1, s ^ 1); CP_COMMIT(); CP_WAIT1(); }
        else           { CP_WAIT0(); }
        __syncthreads();

        const uint32_t aOff = sbase + s * (STAGE_F4 * 16);
        const uint32_t bOff = aOff + 1024 * 16;
#pragma unroll
        for (int ks = 0; ks < 4; ks++) {
            uint32_t a[2][4];
#pragma unroll
            for (int mt = 0; mt < 2; mt++) {
                int row = wm + mt * 16 + (mat & 1) * 8 + mr;
                int c4 = ks * 2 + (mat >> 1);
                uint32_t addr = aOff + (uint32_t)(row * 8 + (c4 ^ (row & 7))) * 16;
                LDSM4(a[mt][0], a[mt][1], a[mt][2], a[mt][3], addr);
            }
            uint32_t b[8][2];
#pragma unroll
            for (int g = 0; g < 4; g++) {
                int row = wn + g * 16 + (mat >> 1) * 8 + mr;
                int c4 = ks * 2 + (mat & 1);
                uint32_t addr = bOff + (uint32_t)(row * 8 + (c4 ^ (row & 7))) * 16;
                LDSM4(b[2 * g][0], b[2 * g][1], b[2 * g + 1][0], b[2 * g + 1][1], addr);
            }
            // round operands to tf32 (rna) to avoid truncation bias
#pragma unroll
            for (int mt = 0; mt < 2; mt++)
#pragma unroll
                for (int j = 0; j < 4; j++) CVT_TF32(a[mt][j]);
#pragma unroll
            for (int nt = 0; nt < 8; nt++)
#pragma unroll
                for (int j = 0; j < 2; j++) CVT_TF32(b[nt][j]);
#pragma unroll
            for (int mt = 0; mt < 2; mt++)
#pragma unroll
                for (int nt = 0; nt < 8; nt++)
                    MMA_TF32(acc[mt][nt], a[mt], b[nt]);
        }
        __syncthreads();
    }

    // Epilogue: d0,d1 at (row, col..col+1), d2,d3 at (row+8, ...)
#pragma unroll
    for (int mt = 0; mt < 2; mt++) {
        int row0 = bm + wm + mt * 16 + (lane >> 2);
#pragma unroll
        for (int nt = 0; nt < 8; nt++) {
            int col = bn + wn + nt * 8 + (lane & 3) * 2;
            float2 v0 = make_float2(acc[mt][nt][0], acc[mt][nt][1]);
            float2 v1 = make_float2(acc[mt][nt][2], acc[mt][nt][3]);
            if (bias) {
                float b0 = bias[col], b1 = bias[col + 1];
                v0.x += b0; v0.y += b1;
                v1.x += b0; v1.y += b1;
            }
            *(float2*)(C + (size_t)row0 * CH + col) = v0;
            *(float2*)(C + (size_t)(row0 + 8) * CH + col) = v1;
        }
    }
}

// ---------------------------------------------------------------------------
// Attention: one block per (b, h). N=64, hd=32.
// ---------------------------------------------------------------------------
__global__ __launch_bounds__(256) void attn_kernel(
    const float* __restrict__ Q, const float* __restrict__ K,
    const float* __restrict__ V, const float* __restrict__ bias_table,
    float* __restrict__ CTX)
{
    __shared__ float qs[SEQ][HDIM];
    __shared__ float ks[SEQ][HDIM];
    __shared__ float vs[SEQ][HDIM];
    __shared__ float sc[SEQ][SEQ];

    int tid = threadIdx.x;
    int b = blockIdx.x >> 4;
    int h = blockIdx.x & 15;

    const size_t base = (size_t)b * SEQ * CH + h * HDIM;
    const float* Qb = Q + base;
    const float* Kb = K + base;
    const float* Vb = V + base;

#pragma unroll
    for (int i = tid; i < SEQ * HDIM / 4; i += 256) {
        int n = i >> 3;
        int d4 = i & 7;
        size_t goff = (size_t)n * CH + d4 * 4;
        ((float4*)&qs[0][0])[i] = *(const float4*)(Qb + goff);
        ((float4*)&ks[0][0])[i] = *(const float4*)(Kb + goff);
        ((float4*)&vs[0][0])[i] = *(const float4*)(Vb + goff);
    }
    __syncthreads();

    const float scale = 0.17677669529663687f;

    {
        int n = tid >> 2;
        int m0 = (tid & 3) * 16;
        int i1 = n >> 3, j1 = n & 7;
#pragma unroll 4
        for (int m = m0; m < m0 + 16; m++) {
            float s = 0.0f;
#pragma unroll
            for (int d = 0; d < HDIM; d++) s = fmaf(qs[n][d], ks[m][d], s);
            int i2 = m >> 3, j2 = m & 7;
            int ridx = (i1 - i2 + 7) * 15 + (j1 - j2 + 7);
            sc[n][m] = s * scale + bias_table[ridx * HEADS + h];
        }
    }
    __syncthreads();

    if (tid < SEQ) {
        int n = tid;
        float mx = -1e30f;
#pragma unroll 8
        for (int m = 0; m < SEQ; m++) mx = fmaxf(mx, sc[n][m]);
        float sum = 0.0f;
#pragma unroll 8
        for (int m = 0; m < SEQ; m++) {
            float e = __expf(sc[n][m] - mx);
            sc[n][m] = e;
            sum += e;
        }
        float inv = 1.0f / sum;
#pragma unroll 8
        for (int m = 0; m < SEQ; m++) sc[n][m] *= inv;
    }
    __syncthreads();

    {
        int n = tid >> 2;
        int d0 = (tid & 3) * 8;
        float accv[8];
#pragma unroll
        for (int j = 0; j < 8; j++) accv[j] = 0.0f;
#pragma unroll 8
        for (int m = 0; m < SEQ; m++) {
            float a = sc[n][m];
#pragma unroll
            for (int j = 0; j < 8; j++) accv[j] = fmaf(a, vs[m][d0 + j], accv[j]);
        }
        float* outp = CTX + base + (size_t)n * CH + d0;
#pragma unroll
        for (int j = 0; j < 8; j += 4)
            *(float4*)(outp + j) = make_float4(accv[j], accv[j + 1], accv[j + 2], accv[j + 3]);
    }
}

// ---------------------------------------------------------------------------
// Launch
// ---------------------------------------------------------------------------
extern "C" void kernel_launch(void* const* d_in, const int* in_sizes, int n_in,
                              void* d_out, int out_size) {
    const float* x          = (const float*)d_in[0];
    const float* Wq         = (const float*)d_in[1];
    const float* Wk_base    = (const float*)d_in[2];
    const float* Wk_spline  = (const float*)d_in[3];
    const float* Wv         = (const float*)d_in[4];
    const float* Wproj      = (const float*)d_in[5];
    const float* bproj      = (const float*)d_in[6];
    const float* bias_table = (const float*)d_in[7];
    float* out = (float*)d_out;

    float *XA, *Qp, *Kp, *Vp, *CTX, *WqT, *WvT, *WpT, *WkT;
    cudaGetSymbolAddress((void**)&XA,  g_XA);
    cudaGetSymbolAddress((void**)&Qp,  g_Q);
    cudaGetSymbolAddress((void**)&Kp,  g_K);
    cudaGetSymbolAddress((void**)&Vp,  g_V);
    cudaGetSymbolAddress((void**)&CTX, g_CTX);
    cudaGetSymbolAddress((void**)&WqT, g_WqT);
    cudaGetSymbolAddress((void**)&WvT, g_WvT);
    cudaGetSymbolAddress((void**)&WpT, g_WpT);
    cudaGetSymbolAddress((void**)&WkT, g_WkT);

    cudaFuncSetAttribute(gemm_tf32_kernel,
                         cudaFuncAttributeMaxDynamicSharedMemorySize, SMEM_TOT);

    // weight prep
    trans512_kernel<<<(CH * CH + 255) / 256, 256>>>(Wq, WqT);
    trans512_kernel<<<(CH * CH + 255) / 256, 256>>>(Wv, WvT);
    trans512_kernel<<<(CH * CH + 255) / 256, 256>>>(Wproj, WpT);
    build_wkt_kernel<<<(CH * XAW + 255) / 256, 256>>>(Wk_base, Wk_spline, WkT);
    // activation prep
    prep_kernel<<<(MROWS * CH + 255) / 256, 256>>>(x, XA);

    dim3 gg(CH / 128, MROWS / 128);   // (4, 256)
    gemm_tf32_kernel<<<gg, 256, SMEM_TOT>>>(x,   CH,  WqT, CH,  Qp,  nullptr);
    gemm_tf32_kernel<<<gg, 256, SMEM_TOT>>>(x,   CH,  WvT, CH,  Vp,  nullptr);
    gemm_tf32_kernel<<<gg, 256, SMEM_TOT>>>(XA,  XAW, WkT, XAW, Kp,  nullptr);

    attn_kernel<<<BATCH * HEADS, 256>>>(Qp, Kp, Vp, bias_table, CTX);

    gemm_tf32_kernel<<<gg, 256, SMEM_TOT>>>(CTX, CH,  WpT, CH,  out, bproj);
}

// round 4
// speedup vs baseline: 2.5576x; 1.0576x over previous
#include <cuda_runtime.h>
#include <cstdint>

// Problem constants
#define BATCH   512
#define SEQ     64
#define CH      512
#define HEADS   16
#define HDIM    32
#define GRIDN   5
#define MROWS   (BATCH * SEQ)          // 32768
#define XAW     (CH * (GRIDN + 1))     // 3072: [swish | phi0 | ... | phi4]

// Scratch (device globals — no allocation allowed)
__device__ float g_XA[(size_t)MROWS * XAW];
__device__ float g_XR[(size_t)MROWS * CH];   // tf32-rounded copy of x
__device__ float g_Q[(size_t)MROWS * CH];
__device__ float g_K[(size_t)MROWS * CH];
__device__ float g_V[(size_t)MROWS * CH];
__device__ float g_CTX[(size_t)MROWS * CH];
__device__ float g_WqT[CH * CH];          // [n][k], tf32-rounded
__device__ float g_WvT[CH * CH];
__device__ float g_WpT[CH * CH];
__device__ float g_WkT[(size_t)CH * XAW]; // [n][3072], tf32-rounded

// ---------------------------------------------------------------------------
// PTX helpers (base sm_103 feature set only: ldmatrix/mma.sync/cp.async)
// ---------------------------------------------------------------------------
__device__ __forceinline__ uint32_t smem_u32(const void* p) {
    uint32_t a;
    asm("{ .reg .u64 t; cvta.to.shared.u64 t, %1; cvt.u32.u64 %0, t; }" : "=r"(a) : "l"(p));
    return a;
}
#define CP_ASYNC16(dst, src) \
    asm volatile("cp.async.cg.shared.global [%0], [%1], 16;" :: "r"(dst), "l"(src))
#define CP_COMMIT() asm volatile("cp.async.commit_group;" ::: "memory")
#define CP_WAIT2()  asm volatile("cp.async.wait_group 2;" ::: "memory")

#define LDSM4(r0, r1, r2, r3, addr) \
    asm volatile("ldmatrix.sync.aligned.m8n8.x4.shared.b16 {%0,%1,%2,%3}, [%4];" \
                 : "=r"(r0), "=r"(r1), "=r"(r2), "=r"(r3) : "r"(addr))

#define MMA_TF32(d, a, b) \
    asm volatile("mma.sync.aligned.m16n8k8.row.col.f32.tf32.tf32.f32 " \
                 "{%0,%1,%2,%3}, {%4,%5,%6,%7}, {%8,%9}, {%0,%1,%2,%3};" \
                 : "+f"((d)[0]), "+f"((d)[1]), "+f"((d)[2]), "+f"((d)[3]) \
                 : "r"((a)[0]), "r"((a)[1]), "r"((a)[2]), "r"((a)[3]), \
                   "r"((b)[0]), "r"((b)[1]))

__device__ __forceinline__ float round_tf32(float f) {
    uint32_t u = __float_as_uint(f);
    asm("cvt.rna.tf32.f32 %0, %0;" : "+r"(u));
    return __uint_as_float(u);
}

// ---------------------------------------------------------------------------
// Prep: XR = round(x); XA[m,c] = round(swish(x));
//       XA[m, 512 + g*512 + c] = round(exp(-(x-(g-2))^2))
// ---------------------------------------------------------------------------
__global__ __launch_bounds__(256) void prep_kernel(const float* __restrict__ x,
                                                   float* __restrict__ XA,
                                                   float* __restrict__ XR) {
    int idx = blockIdx.x * blockDim.x + threadIdx.x;
    if (idx >= MROWS * CH) return;
    int m = idx >> 9;
    int c = idx & 511;
    float v = x[idx];
    XR[idx] = round_tf32(v);
    float* row = XA + (size_t)m * XAW;
    row[c] = round_tf32(v / (1.0f + __expf(-v)));
#pragma unroll
    for (int g = 0; g < GRIDN; g++) {
        float d = v - (float)(g - 2);
        row[CH + g * CH + c] = round_tf32(__expf(-d * d));
    }
}

// ---------------------------------------------------------------------------
// Weight transposes: WT[n,k] = round(W[k,n])
// ---------------------------------------------------------------------------
__global__ __launch_bounds__(256) void trans512_kernel(const float* __restrict__ W,
                                                       float* __restrict__ WT) {
    int idx = blockIdx.x * blockDim.x + threadIdx.x;
    if (idx >= CH * CH) return;
    int n = idx >> 9;
    int k = idx & 511;
    WT[idx] = round_tf32(W[k * CH + n]);
}

// WkT[n][k]: k<512 -> Wk_base[k][n]; k=512+g*512+c -> Wk_spline[c*5+g][n]
__global__ __launch_bounds__(256) void build_wkt_kernel(const float* __restrict__ Wb,
                                                        const float* __restrict__ Ws,
                                                        float* __restrict__ WkT) {
    int idx = blockIdx.x * blockDim.x + threadIdx.x;
    if (idx >= CH * XAW) return;
    int n = idx / XAW;
    int k = idx - n * XAW;
    float v;
    if (k < CH) {
        v = Wb[k * CH + n];
    } else {
        int kk = k - CH;
        int g = kk >> 9;
        int c = kk & 511;
        v = Ws[(c * GRIDN + g) * CH + n];
    }
    WkT[idx] = round_tf32(v);
}

// ---------------------------------------------------------------------------
// tf32 mma.sync GEMM: C[M, 512] = A[M, K] @ Bt[512, K]^T (+bias)
// BM=BN=128, BK=32; 8 warps (4 x 2), warp tile 32x64; ldmatrix + cp.async x3.
// Operands are PRE-ROUNDED to tf32 — no cvt in inner loop.
// XOR swizzle within 128B rows: float4 idx = row*8 + (c4 ^ (row&7)).
// ---------------------------------------------------------------------------
#define BK        32
#define STAGE_B   32768
#define NSTAGE    3
#define SMEM_TOT  (NSTAGE * STAGE_B)   // 98304

__global__ __launch_bounds__(256, 2) void gemm_tf32_kernel(
    const float* __restrict__ A, int lda,
    const float* __restrict__ Bt, int K,
    float* __restrict__ C,
    const float* __restrict__ bias)
{
    extern __shared__ __align__(16) float4 sm4[];
    const uint32_t sbase = smem_u32(sm4);
    const int tid = threadIdx.x;
    const int bm = blockIdx.y * 128;
    const int bn = blockIdx.x * 128;
    const int NC = K / BK;

    const int lane = tid & 31, wid = tid >> 5;
    const int wm = (wid & 3) * 32;         // warp row offset
    const int wn = (wid >> 2) * 64;        // warp col offset
    const int mat = lane >> 3, mr = lane & 7;

    float acc[2][8][4];
#pragma unroll
    for (int mt = 0; mt < 2; mt++)
#pragma unroll
        for (int nt = 0; nt < 8; nt++)
#pragma unroll
            for (int j = 0; j < 4; j++) acc[mt][nt][j] = 0.0f;

    auto load_chunk = [&](int c, int s) {
        const float* Ak = A + (size_t)bm * lda + c * BK;
        const float* Bk = Bt + (size_t)bn * K + c * BK;
        const uint32_t aOff = sbase + s * STAGE_B;
        const uint32_t bOff = aOff + 16384;
#pragma unroll
        for (int i = 0; i < 4; i++) {
            int u = tid + 256 * i;
            int row = u >> 3, c4 = u & 7;
            uint32_t d = aOff + (uint32_t)(row * 8 + (c4 ^ (row & 7))) * 16;
            CP_ASYNC16(d, Ak + (size_t)row * lda + c4 * 4);
        }
#pragma unroll
        for (int i = 0; i < 4; i++) {
            int u = tid + 256 * i;
            int row = u >> 3, c4 = u & 7;
            uint32_t d = bOff + (uint32_t)(row * 8 + (c4 ^ (row & 7))) * 16;
            CP_ASYNC16(d, Bk + (size_t)row * K + c4 * 4);
        }
    };

    load_chunk(0, 0); CP_COMMIT();
    load_chunk(1, 1); CP_COMMIT();

    int s = 0;
    for (int c = 0; c < NC; c++) {
        if (c + 2 < NC) {
            int s2 = s + 2; if (s2 >= NSTAGE) s2 -= NSTAGE;
            load_chunk(c + 2, s2);
        }
        CP_COMMIT();
        CP_WAIT2();
        __syncthreads();

        const uint32_t aOff = sbase + s * STAGE_B;
        const uint32_t bOff = aOff + 16384;
#pragma unroll
        for (int ks = 0; ks < 4; ks++) {
            uint32_t a[2][4];
#pragma unroll
            for (int mt = 0; mt < 2; mt++) {
                int row = wm + mt * 16 + (mat & 1) * 8 + mr;
                int c4 = ks * 2 + (mat >> 1);
                uint32_t addr = aOff + (uint32_t)(row * 8 + (c4 ^ (row & 7))) * 16;
                LDSM4(a[mt][0], a[mt][1], a[mt][2], a[mt][3], addr);
            }
            uint32_t b[8][2];
#pragma unroll
            for (int g = 0; g < 4; g++) {
                int row = wn + g * 16 + (mat >> 1) * 8 + mr;
                int c4 = ks * 2 + (mat & 1);
                uint32_t addr = bOff + (uint32_t)(row * 8 + (c4 ^ (row & 7))) * 16;
                LDSM4(b[2 * g][0], b[2 * g][1], b[2 * g + 1][0], b[2 * g + 1][1], addr);
            }
#pragma unroll
            for (int mt = 0; mt < 2; mt++)
#pragma unroll
                for (int nt = 0; nt < 8; nt++)
                    MMA_TF32(acc[mt][nt], a[mt], b[nt]);
        }
        __syncthreads();
        if (++s >= NSTAGE) s = 0;
    }

    // Epilogue: d0,d1 at (row, col..col+1), d2,d3 at (row+8, ...)
#pragma unroll
    for (int mt = 0; mt < 2; mt++) {
        int row0 = bm + wm + mt * 16 + (lane >> 2);
#pragma unroll
        for (int nt = 0; nt < 8; nt++) {
            int col = bn + wn + nt * 8 + (lane & 3) * 2;
            float2 v0 = make_float2(acc[mt][nt][0], acc[mt][nt][1]);
            float2 v1 = make_float2(acc[mt][nt][2], acc[mt][nt][3]);
            if (bias) {
                float b0 = bias[col], b1 = bias[col + 1];
                v0.x += b0; v0.y += b1;
                v1.x += b0; v1.y += b1;
            }
            *(float2*)(C + (size_t)row0 * CH + col) = v0;
            *(float2*)(C + (size_t)(row0 + 8) * CH + col) = v1;
        }
    }
}

// ---------------------------------------------------------------------------
// Attention: one block per (b, h). N=64, hd=32. CTX is tf32-rounded on store.
// ---------------------------------------------------------------------------
__global__ __launch_bounds__(256) void attn_kernel(
    const float* __restrict__ Q, const float* __restrict__ K,
    const float* __restrict__ V, const float* __restrict__ bias_table,
    float* __restrict__ CTX)
{
    __shared__ float qs[SEQ][HDIM];
    __shared__ float ks[SEQ][HDIM];
    __shared__ float vs[SEQ][HDIM];
    __shared__ float sc[SEQ][SEQ];

    int tid = threadIdx.x;
    int b = blockIdx.x >> 4;
    int h = blockIdx.x & 15;

    const size_t base = (size_t)b * SEQ * CH + h * HDIM;
    const float* Qb = Q + base;
    const float* Kb = K + base;
    const float* Vb = V + base;

#pragma unroll
    for (int i = tid; i < SEQ * HDIM / 4; i += 256) {
        int n = i >> 3;
        int d4 = i & 7;
        size_t goff = (size_t)n * CH + d4 * 4;
        ((float4*)&qs[0][0])[i] = *(const float4*)(Qb + goff);
        ((float4*)&ks[0][0])[i] = *(const float4*)(Kb + goff);
        ((float4*)&vs[0][0])[i] = *(const float4*)(Vb + goff);
    }
    __syncthreads();

    const float scale = 0.17677669529663687f;

    {
        int n = tid >> 2;
        int m0 = (tid & 3) * 16;
        int i1 = n >> 3, j1 = n & 7;
#pragma unroll 4
        for (int m = m0; m < m0 + 16; m++) {
            float s = 0.0f;
#pragma unroll
            for (int d = 0; d < HDIM; d++) s = fmaf(qs[n][d], ks[m][d], s);
            int i2 = m >> 3, j2 = m & 7;
            int ridx = (i1 - i2 + 7) * 15 + (j1 - j2 + 7);
            sc[n][m] = s * scale + bias_table[ridx * HEADS + h];
        }
    }
    __syncthreads();

    if (tid < SEQ) {
        int n = tid;
        float mx = -1e30f;
#pragma unroll 8
        for (int m = 0; m < SEQ; m++) mx = fmaxf(mx, sc[n][m]);
        float sum = 0.0f;
#pragma unroll 8
        for (int m = 0; m < SEQ; m++) {
            float e = __expf(sc[n][m] - mx);
            sc[n][m] = e;
            sum += e;
        }
        float inv = 1.0f / sum;
#pragma unroll 8
        for (int m = 0; m < SEQ; m++) sc[n][m] *= inv;
    }
    __syncthreads();

    {
        int n = tid >> 2;
        int d0 = (tid & 3) * 8;
        float accv[8];
#pragma unroll
        for (int j = 0; j < 8; j++) accv[j] = 0.0f;
#pragma unroll 8
        for (int m = 0; m < SEQ; m++) {
            float a = sc[n][m];
#pragma unroll
            for (int j = 0; j < 8; j++) accv[j] = fmaf(a, vs[m][d0 + j], accv[j]);
        }
        float* outp = CTX + base + (size_t)n * CH + d0;
#pragma unroll
        for (int j = 0; j < 8; j++) accv[j] = round_tf32(accv[j]);
#pragma unroll
        for (int j = 0; j < 8; j += 4)
            *(float4*)(outp + j) = make_float4(accv[j], accv[j + 1], accv[j + 2], accv[j + 3]);
    }
}

// ---------------------------------------------------------------------------
// Launch
// ---------------------------------------------------------------------------
extern "C" void kernel_launch(void* const* d_in, const int* in_sizes, int n_in,
                              void* d_out, int out_size) {
    const float* x          = (const float*)d_in[0];
    const float* Wq         = (const float*)d_in[1];
    const float* Wk_base    = (const float*)d_in[2];
    const float* Wk_spline  = (const float*)d_in[3];
    const float* Wv         = (const float*)d_in[4];
    const float* Wproj      = (const float*)d_in[5];
    const float* bproj      = (const float*)d_in[6];
    const float* bias_table = (const float*)d_in[7];
    float* out = (float*)d_out;

    float *XA, *XR, *Qp, *Kp, *Vp, *CTX, *WqT, *WvT, *WpT, *WkT;
    cudaGetSymbolAddress((void**)&XA,  g_XA);
    cudaGetSymbolAddress((void**)&XR,  g_XR);
    cudaGetSymbolAddress((void**)&Qp,  g_Q);
    cudaGetSymbolAddress((void**)&Kp,  g_K);
    cudaGetSymbolAddress((void**)&Vp,  g_V);
    cudaGetSymbolAddress((void**)&CTX, g_CTX);
    cudaGetSymbolAddress((void**)&WqT, g_WqT);
    cudaGetSymbolAddress((void**)&WvT, g_WvT);
    cudaGetSymbolAddress((void**)&WpT, g_WpT);
    cudaGetSymbolAddress((void**)&WkT, g_WkT);

    cudaFuncSetAttribute(gemm_tf32_kernel,
                         cudaFuncAttributeMaxDynamicSharedMemorySize, SMEM_TOT);

    // weight prep
    trans512_kernel<<<(CH * CH + 255) / 256, 256>>>(Wq, WqT);
    trans512_kernel<<<(CH * CH + 255) / 256, 256>>>(Wv, WvT);
    trans512_kernel<<<(CH * CH + 255) / 256, 256>>>(Wproj, WpT);
    build_wkt_kernel<<<(CH * XAW + 255) / 256, 256>>>(Wk_base, Wk_spline, WkT);
    // activation prep
    prep_kernel<<<(MROWS * CH + 255) / 256, 256>>>(x, XA, XR);

    dim3 gg(CH / 128, MROWS / 128);   // (4, 256)
    gemm_tf32_kernel<<<gg, 256, SMEM_TOT>>>(XR,  CH,  WqT, CH,  Qp,  nullptr);
    gemm_tf32_kernel<<<gg, 256, SMEM_TOT>>>(XR,  CH,  WvT, CH,  Vp,  nullptr);
    gemm_tf32_kernel<<<gg, 256, SMEM_TOT>>>(XA,  XAW, WkT, XAW, Kp,  nullptr);

    attn_kernel<<<BATCH * HEADS, 256>>>(Qp, Kp, Vp, bias_table, CTX);

    gemm_tf32_kernel<<<gg, 256, SMEM_TOT>>>(CTX, CH,  WpT, CH,  out, bproj);
}

// round 5
// speedup vs baseline: 3.1177x; 1.2190x over previous
#include <cuda_runtime.h>
#include <cuda_fp16.h>
#include <cstdint>

// Problem constants
#define BATCH   512
#define SEQ     64
#define CH      512
#define HEADS   16
#define HDIM    32
#define GRIDN   5
#define MROWS   (BATCH * SEQ)          // 32768
#define XAW     (CH * (GRIDN + 1))     // 3072: [swish | phi0 | ... | phi4]

// Scratch (device globals — no allocation allowed)
__device__ __align__(16) __half g_XA[(size_t)MROWS * XAW];
__device__ __align__(16) __half g_XR[(size_t)MROWS * CH];
__device__ float  g_Q[(size_t)MROWS * CH];
__device__ float  g_K[(size_t)MROWS * CH];
__device__ float  g_V[(size_t)MROWS * CH];
__device__ __align__(16) __half g_CTX[(size_t)MROWS * CH];
__device__ __align__(16) __half g_WqT[CH * CH];          // [n][k]
__device__ __align__(16) __half g_WvT[CH * CH];
__device__ __align__(16) __half g_WpT[CH * CH];
__device__ __align__(16) __half g_WkT[(size_t)CH * XAW]; // [n][3072]

// ---------------------------------------------------------------------------
// PTX helpers
// ---------------------------------------------------------------------------
__device__ __forceinline__ uint32_t smem_u32(const void* p) {
    uint32_t a;
    asm("{ .reg .u64 t; cvta.to.shared.u64 t, %1; cvt.u32.u64 %0, t; }" : "=r"(a) : "l"(p));
    return a;
}
#define CP_ASYNC16(dst, src) \
    asm volatile("cp.async.cg.shared.global [%0], [%1], 16;" :: "r"(dst), "l"(src))
#define CP_COMMIT() asm volatile("cp.async.commit_group;" ::: "memory")
#define CP_WAIT2()  asm volatile("cp.async.wait_group 2;" ::: "memory")

#define LDSM4(r0, r1, r2, r3, addr) \
    asm volatile("ldmatrix.sync.aligned.m8n8.x4.shared.b16 {%0,%1,%2,%3}, [%4];" \
                 : "=r"(r0), "=r"(r1), "=r"(r2), "=r"(r3) : "r"(addr))

#define MMA_F16(d, a, b) \
    asm volatile("mma.sync.aligned.m16n8k16.row.col.f32.f16.f16.f32 " \
                 "{%0,%1,%2,%3}, {%4,%5,%6,%7}, {%8,%9}, {%0,%1,%2,%3};" \
                 : "+f"((d)[0]), "+f"((d)[1]), "+f"((d)[2]), "+f"((d)[3]) \
                 : "r"((a)[0]), "r"((a)[1]), "r"((a)[2]), "r"((a)[3]), \
                   "r"((b)[0]), "r"((b)[1]))

// ---------------------------------------------------------------------------
// Prep: XR = half(x); XA[m,c] = half(swish(x));
//       XA[m, 512 + g*512 + c] = half(exp(-(x-(g-2))^2))
// ---------------------------------------------------------------------------
__global__ __launch_bounds__(256) void prep_kernel(const float* __restrict__ x,
                                                   __half* __restrict__ XA,
                                                   __half* __restrict__ XR) {
    int idx = blockIdx.x * blockDim.x + threadIdx.x;
    if (idx >= MROWS * CH) return;
    int m = idx >> 9;
    int c = idx & 511;
    float v = x[idx];
    XR[idx] = __float2half_rn(v);
    __half* row = XA + (size_t)m * XAW;
    row[c] = __float2half_rn(v / (1.0f + __expf(-v)));
#pragma unroll
    for (int g = 0; g < GRIDN; g++) {
        float d = v - (float)(g - 2);
        row[CH + g * CH + c] = __float2half_rn(__expf(-d * d));
    }
}

// ---------------------------------------------------------------------------
// Weight transposes: WT[n,k] = half(W[k,n])
// ---------------------------------------------------------------------------
__global__ __launch_bounds__(256) void trans512_kernel(const float* __restrict__ W,
                                                       __half* __restrict__ WT) {
    int idx = blockIdx.x * blockDim.x + threadIdx.x;
    if (idx >= CH * CH) return;
    int n = idx >> 9;
    int k = idx & 511;
    WT[idx] = __float2half_rn(W[k * CH + n]);
}

// WkT[n][k]: k<512 -> Wk_base[k][n]; k=512+g*512+c -> Wk_spline[c*5+g][n]
__global__ __launch_bounds__(256) void build_wkt_kernel(const float* __restrict__ Wb,
                                                        const float* __restrict__ Ws,
                                                        __half* __restrict__ WkT) {
    int idx = blockIdx.x * blockDim.x + threadIdx.x;
    if (idx >= CH * XAW) return;
    int n = idx / XAW;
    int k = idx - n * XAW;
    float v;
    if (k < CH) {
        v = Wb[k * CH + n];
    } else {
        int kk = k - CH;
        int g = kk >> 9;
        int c = kk & 511;
        v = Ws[(c * GRIDN + g) * CH + n];
    }
    WkT[idx] = __float2half_rn(v);
}

// ---------------------------------------------------------------------------
// fp16 mma.sync GEMM: C[M, 512](f32) = A[M, K](f16) @ Bt[512, K](f16)^T (+bias)
// BM=BN=128, BK=64 halves (128B rows); 8 warps (4x2), warp tile 32x64.
// 3-stage cp.async. XOR swizzle: unit16 idx = row*8 + (c8 ^ (row&7)).
// ---------------------------------------------------------------------------
#define BK        64
#define STAGE_B   32768                 // A 16KB + B 16KB
#define NSTAGE    3
#define SMEM_TOT  (NSTAGE * STAGE_B)    // 98304

__global__ __launch_bounds__(256, 2) void gemm_f16_kernel(
    const __half* __restrict__ A, int lda,
    const __half* __restrict__ Bt, int K,
    float* __restrict__ C,
    const float* __restrict__ bias)
{
    extern __shared__ __align__(16) char smc[];
    const uint32_t sbase = smem_u32(smc);
    const int tid = threadIdx.x;
    const int bm = blockIdx.y * 128;
    const int bn = blockIdx.x * 128;
    const int NC = K / BK;

    const int lane = tid & 31, wid = tid >> 5;
    const int wm = (wid & 3) * 32;         // warp row offset
    const int wn = (wid >> 2) * 64;        // warp col offset

    float acc[2][8][4];
#pragma unroll
    for (int mt = 0; mt < 2; mt++)
#pragma unroll
        for (int nt = 0; nt < 8; nt++)
#pragma unroll
            for (int j = 0; j < 4; j++) acc[mt][nt][j] = 0.0f;

    auto load_chunk = [&](int c, int s) {
        const __half* Ak = A + (size_t)bm * lda + c * BK;
        const __half* Bk = Bt + (size_t)bn * K + c * BK;
        const uint32_t aOff = sbase + s * STAGE_B;
        const uint32_t bOff = aOff + 16384;
#pragma unroll
        for (int i = 0; i < 4; i++) {
            int u = tid + 256 * i;
            int row = u >> 3, c8 = u & 7;
            uint32_t d = aOff + (uint32_t)(row * 8 + (c8 ^ (row & 7))) * 16;
            CP_ASYNC16(d, Ak + (size_t)row * lda + c8 * 8);
        }
#pragma unroll
        for (int i = 0; i < 4; i++) {
            int u = tid + 256 * i;
            int row = u >> 3, c8 = u & 7;
            uint32_t d = bOff + (uint32_t)(row * 8 + (c8 ^ (row & 7))) * 16;
            CP_ASYNC16(d, Bk + (size_t)row * K + c8 * 8);
        }
    };

    load_chunk(0, 0); CP_COMMIT();
    load_chunk(1, 1); CP_COMMIT();

    int s = 0;
    for (int c = 0; c < NC; c++) {
        if (c + 2 < NC) {
            int s2 = s + 2; if (s2 >= NSTAGE) s2 -= NSTAGE;
            load_chunk(c + 2, s2);
        }
        CP_COMMIT();
        CP_WAIT2();
        __syncthreads();

        const uint32_t aOff = sbase + s * STAGE_B;
        const uint32_t bOff = aOff + 16384;
#pragma unroll
        for (int ks = 0; ks < 4; ks++) {
            // A fragments: 16x16 per mt-tile, canonical x4
            uint32_t a[2][4];
#pragma unroll
            for (int mt = 0; mt < 2; mt++) {
                int row = wm + mt * 16 + (lane & 15);
                int c8 = ks * 2 + (lane >> 4);
                uint32_t addr = aOff + (uint32_t)((row * 8 + (c8 ^ (row & 7))) << 4);
                LDSM4(a[mt][0], a[mt][1], a[mt][2], a[mt][3], addr);
            }
            // B fragments: each x4 yields b-frags for two n8-tiles
            uint32_t b[8][2];
#pragma unroll
            for (int g = 0; g < 4; g++) {
                int row = wn + g * 16 + (lane & 7) + ((lane & 16) >> 1);
                int c8 = ks * 2 + ((lane >> 3) & 1);
                uint32_t addr = bOff + (uint32_t)((row * 8 + (c8 ^ (row & 7))) << 4);
                LDSM4(b[2 * g][0], b[2 * g][1], b[2 * g + 1][0], b[2 * g + 1][1], addr);
            }
#pragma unroll
            for (int mt = 0; mt < 2; mt++)
#pragma unroll
                for (int nt = 0; nt < 8; nt++)
                    MMA_F16(acc[mt][nt], a[mt], b[nt]);
        }
        __syncthreads();
        if (++s >= NSTAGE) s = 0;
    }

    // Epilogue: d0,d1 at (row, col..col+1), d2,d3 at (row+8, ...)
#pragma unroll
    for (int mt = 0; mt < 2; mt++) {
        int row0 = bm + wm + mt * 16 + (lane >> 2);
#pragma unroll
        for (int nt = 0; nt < 8; nt++) {
            int col = bn + wn + nt * 8 + (lane & 3) * 2;
            float2 v0 = make_float2(acc[mt][nt][0], acc[mt][nt][1]);
            float2 v1 = make_float2(acc[mt][nt][2], acc[mt][nt][3]);
            if (bias) {
                float b0 = bias[col], b1 = bias[col + 1];
                v0.x += b0; v0.y += b1;
                v1.x += b0; v1.y += b1;
            }
            *(float2*)(C + (size_t)row0 * CH + col) = v0;
            *(float2*)(C + (size_t)(row0 + 8) * CH + col) = v1;
        }
    }
}

// ---------------------------------------------------------------------------
// Attention: one block per (b, h). N=64, hd=32. CTX stored as half.
// ---------------------------------------------------------------------------
__global__ __launch_bounds__(256) void attn_kernel(
    const float* __restrict__ Q, const float* __restrict__ K,
    const float* __restrict__ V, const float* __restrict__ bias_table,
    __half* __restrict__ CTX)
{
    __shared__ float qs[SEQ][HDIM];
    __shared__ float ks[SEQ][HDIM];
    __shared__ float vs[SEQ][HDIM];
    __shared__ float sc[SEQ][SEQ];

    int tid = threadIdx.x;
    int b = blockIdx.x >> 4;
    int h = blockIdx.x & 15;

    const size_t base = (size_t)b * SEQ * CH + h * HDIM;
    const float* Qb = Q + base;
    const float* Kb = K + base;
    const float* Vb = V + base;

#pragma unroll
    for (int i = tid; i < SEQ * HDIM / 4; i += 256) {
        int n = i >> 3;
        int d4 = i & 7;
        size_t goff = (size_t)n * CH + d4 * 4;
        ((float4*)&qs[0][0])[i] = *(const float4*)(Qb + goff);
        ((float4*)&ks[0][0])[i] = *(const float4*)(Kb + goff);
        ((float4*)&vs[0][0])[i] = *(const float4*)(Vb + goff);
    }
    __syncthreads();

    const float scale = 0.17677669529663687f;

    {
        int n = tid >> 2;
        int m0 = (tid & 3) * 16;
        int i1 = n >> 3, j1 = n & 7;
#pragma unroll 4
        for (int m = m0; m < m0 + 16; m++) {
            float s = 0.0f;
#pragma unroll
            for (int d = 0; d < HDIM; d++) s = fmaf(qs[n][d], ks[m][d], s);
            int i2 = m >> 3, j2 = m & 7;
            int ridx = (i1 - i2 + 7) * 15 + (j1 - j2 + 7);
            sc[n][m] = s * scale + bias_table[ridx * HEADS + h];
        }
    }
    __syncthreads();

    if (tid < SEQ) {
        int n = tid;
        float mx = -1e30f;
#pragma unroll 8
        for (int m = 0; m < SEQ; m++) mx = fmaxf(mx, sc[n][m]);
        float sum = 0.0f;
#pragma unroll 8
        for (int m = 0; m < SEQ; m++) {
            float e = __expf(sc[n][m] - mx);
            sc[n][m] = e;
            sum += e;
        }
        float inv = 1.0f / sum;
#pragma unroll 8
        for (int m = 0; m < SEQ; m++) sc[n][m] *= inv;
    }
    __syncthreads();

    {
        int n = tid >> 2;
        int d0 = (tid & 3) * 8;
        float accv[8];
#pragma unroll
        for (int j = 0; j < 8; j++) accv[j] = 0.0f;
#pragma unroll 8
        for (int m = 0; m < SEQ; m++) {
            float a = sc[n][m];
#pragma unroll
            for (int j = 0; j < 8; j++) accv[j] = fmaf(a, vs[m][d0 + j], accv[j]);
        }
        __half2 hv[4];
#pragma unroll
        for (int j = 0; j < 4; j++)
            hv[j] = __floats2half2_rn(accv[2 * j], accv[2 * j + 1]);
        *(float4*)(CTX + base + (size_t)n * CH + d0) = *(float4*)hv;
    }
}

// ---------------------------------------------------------------------------
// Launch
// ---------------------------------------------------------------------------
extern "C" void kernel_launch(void* const* d_in, const int* in_sizes, int n_in,
                              void* d_out, int out_size) {
    const float* x          = (const float*)d_in[0];
    const float* Wq         = (const float*)d_in[1];
    const float* Wk_base    = (const float*)d_in[2];
    const float* Wk_spline  = (const float*)d_in[3];
    const float* Wv         = (const float*)d_in[4];
    const float* Wproj      = (const float*)d_in[5];
    const float* bproj      = (const float*)d_in[6];
    const float* bias_table = (const float*)d_in[7];
    float* out = (float*)d_out;

    __half *XA, *XR, *CTX, *WqT, *WvT, *WpT, *WkT;
    float *Qp, *Kp, *Vp;
    cudaGetSymbolAddress((void**)&XA,  g_XA);
    cudaGetSymbolAddress((void**)&XR,  g_XR);
    cudaGetSymbolAddress((void**)&Qp,  g_Q);
    cudaGetSymbolAddress((void**)&Kp,  g_K);
    cudaGetSymbolAddress((void**)&Vp,  g_V);
    cudaGetSymbolAddress((void**)&CTX, g_CTX);
    cudaGetSymbolAddress((void**)&WqT, g_WqT);
    cudaGetSymbolAddress((void**)&WvT, g_WvT);
    cudaGetSymbolAddress((void**)&WpT, g_WpT);
    cudaGetSymbolAddress((void**)&WkT, g_WkT);

    cudaFuncSetAttribute(gemm_f16_kernel,
                         cudaFuncAttributeMaxDynamicSharedMemorySize, SMEM_TOT);

    // weight prep
    trans512_kernel<<<(CH * CH + 255) / 256, 256>>>(Wq, WqT);
    trans512_kernel<<<(CH * CH + 255) / 256, 256>>>(Wv, WvT);
    trans512_kernel<<<(CH * CH + 255) / 256, 256>>>(Wproj, WpT);
    build_wkt_kernel<<<(CH * XAW + 255) / 256, 256>>>(Wk_base, Wk_spline, WkT);
    // activation prep
    prep_kernel<<<(MROWS * CH + 255) / 256, 256>>>(x, XA, XR);

    dim3 gg(CH / 128, MROWS / 128);   // (4, 256)
    gemm_f16_kernel<<<gg, 256, SMEM_TOT>>>(XR,  CH,  WqT, CH,  Qp,  nullptr);
    gemm_f16_kernel<<<gg, 256, SMEM_TOT>>>(XR,  CH,  WvT, CH,  Vp,  nullptr);
    gemm_f16_kernel<<<gg, 256, SMEM_TOT>>>(XA,  XAW, WkT, XAW, Kp,  nullptr);

    attn_kernel<<<BATCH * HEADS, 256>>>(Qp, Kp, Vp, bias_table, CTX);

    gemm_f16_kernel<<<gg, 256, SMEM_TOT>>>(CTX, CH,  WpT, CH,  out, bproj);
}

// round 6
// speedup vs baseline: 9.4666x; 3.0364x over previous
#include <cuda_runtime.h>
#include <cuda_fp16.h>
#include <cstdint>

// Problem constants
#define BATCH   512
#define SEQ     64
#define CH      512
#define HEADS   16
#define HDIM    32
#define GRIDN   5
#define MROWS   (BATCH * SEQ)          // 32768
#define XAW     (CH * (GRIDN + 1))     // 3072: [swish | phi0 | ... | phi4]

// Scratch (device globals — no allocation allowed)
__device__ __align__(16) __half g_XA[(size_t)MROWS * XAW];
__device__ __align__(16) __half g_XR[(size_t)MROWS * CH];
__device__ __align__(16) __half g_Q[(size_t)MROWS * CH];
__device__ __align__(16) __half g_K[(size_t)MROWS * CH];
__device__ __align__(16) __half g_V[(size_t)MROWS * CH];
__device__ __align__(16) __half g_CTX[(size_t)MROWS * CH];
__device__ __align__(16) __half g_WqT[CH * CH];          // [n][k]
__device__ __align__(16) __half g_WvT[CH * CH];
__device__ __align__(16) __half g_WpT[CH * CH];
__device__ __align__(16) __half g_WkT[(size_t)CH * XAW]; // [n][3072]
__device__ __align__(16) __half g_B64[HEADS * SEQ * SEQ]; // per-head bias [h][n][m]

// ---------------------------------------------------------------------------
// PTX helpers
// ---------------------------------------------------------------------------
__device__ __forceinline__ uint32_t smem_u32(const void* p) {
    uint32_t a;
    asm("{ .reg .u64 t; cvta.to.shared.u64 t, %1; cvt.u32.u64 %0, t; }" : "=r"(a) : "l"(p));
    return a;
}
#define CP_ASYNC16(dst, src) \
    asm volatile("cp.async.cg.shared.global [%0], [%1], 16;" :: "r"(dst), "l"(src))
#define CP_COMMIT() asm volatile("cp.async.commit_group;" ::: "memory")
#define CP_WAIT2()  asm volatile("cp.async.wait_group 2;" ::: "memory")

#define LDSM4(r0, r1, r2, r3, addr) \
    asm volatile("ldmatrix.sync.aligned.m8n8.x4.shared.b16 {%0,%1,%2,%3}, [%4];" \
                 : "=r"(r0), "=r"(r1), "=r"(r2), "=r"(r3) : "r"(addr))

#define MMA_F16(d, a, b) \
    asm volatile("mma.sync.aligned.m16n8k16.row.col.f32.f16.f16.f32 " \
                 "{%0,%1,%2,%3}, {%4,%5,%6,%7}, {%8,%9}, {%0,%1,%2,%3};" \
                 : "+f"((d)[0]), "+f"((d)[1]), "+f"((d)[2]), "+f"((d)[3]) \
                 : "r"((a)[0]), "r"((a)[1]), "r"((a)[2]), "r"((a)[3]), \
                   "r"((b)[0]), "r"((b)[1]))

// ---------------------------------------------------------------------------
// Prep: XR = half(x); XA[m,c] = half(swish(x));
//       XA[m, 512 + g*512 + c] = half(exp(-(x-(g-2))^2))
// ---------------------------------------------------------------------------
__global__ __launch_bounds__(256) void prep_kernel(const float* __restrict__ x,
                                                   __half* __restrict__ XA,
                                                   __half* __restrict__ XR) {
    int idx = blockIdx.x * blockDim.x + threadIdx.x;
    if (idx >= MROWS * CH) return;
    int m = idx >> 9;
    int c = idx & 511;
    float v = x[idx];
    XR[idx] = __float2half_rn(v);
    __half* row = XA + (size_t)m * XAW;
    row[c] = __float2half_rn(v / (1.0f + __expf(-v)));
#pragma unroll
    for (int g = 0; g < GRIDN; g++) {
        float d = v - (float)(g - 2);
        row[CH + g * CH + c] = __float2half_rn(__expf(-d * d));
    }
}

// ---------------------------------------------------------------------------
// Weight transposes: WT[n,k] = half(W[k,n])
// ---------------------------------------------------------------------------
__global__ __launch_bounds__(256) void trans512_kernel(const float* __restrict__ W,
                                                       __half* __restrict__ WT) {
    int idx = blockIdx.x * blockDim.x + threadIdx.x;
    if (idx >= CH * CH) return;
    int n = idx >> 9;
    int k = idx & 511;
    WT[idx] = __float2half_rn(W[k * CH + n]);
}

// WkT[n][k]: k<512 -> Wk_base[k][n]; k=512+g*512+c -> Wk_spline[c*5+g][n]
__global__ __launch_bounds__(256) void build_wkt_kernel(const float* __restrict__ Wb,
                                                        const float* __restrict__ Ws,
                                                        __half* __restrict__ WkT) {
    int idx = blockIdx.x * blockDim.x + threadIdx.x;
    if (idx >= CH * XAW) return;
    int n = idx / XAW;
    int k = idx - n * XAW;
    float v;
    if (k < CH) {
        v = Wb[k * CH + n];
    } else {
        int kk = k - CH;
        int g = kk >> 9;
        int c = kk & 511;
        v = Ws[(c * GRIDN + g) * CH + n];
    }
    WkT[idx] = __float2half_rn(v);
}

// Per-head relative-position bias table: B64[h][n][m] (half)
__global__ __launch_bounds__(256) void build_b64_kernel(const float* __restrict__ bt,
                                                        __half* __restrict__ B64) {
    int idx = blockIdx.x * blockDim.x + threadIdx.x;
    if (idx >= HEADS * SEQ * SEQ) return;
    int h = idx >> 12;
    int nm = idx & 4095;
    int n = nm >> 6, m = nm & 63;
    int i1 = n >> 3, j1 = n & 7;
    int i2 = m >> 3, j2 = m & 7;
    int ridx = (i1 - i2 + 7) * 15 + (j1 - j2 + 7);
    B64[idx] = __float2half_rn(bt[ridx * HEADS + h]);
}

// ---------------------------------------------------------------------------
// fp16 mma.sync GEMM: C[M, 512] = alpha * A[M, K](f16) @ Bt[512, K](f16)^T (+bias)
// Output type templated (half for Q/K/V, float for proj).
// BM=BN=128, BK=64; 8 warps (4x2), warp tile 32x64; 3-stage cp.async.
// ---------------------------------------------------------------------------
#define BK        64
#define STAGE_B   32768                 // A 16KB + B 16KB
#define NSTAGE    3
#define SMEM_TOT  (NSTAGE * STAGE_B)    // 98304

template <typename OT>
__global__ __launch_bounds__(256, 2) void gemm_f16_kernel(
    const __half* __restrict__ A, int lda,
    const __half* __restrict__ Bt, int K,
    OT* __restrict__ C,
    const float* __restrict__ bias, float alpha)
{
    extern __shared__ __align__(16) char smc[];
    const uint32_t sbase = smem_u32(smc);
    const int tid = threadIdx.x;
    const int bm = blockIdx.y * 128;
    const int bn = blockIdx.x * 128;
    const int NC = K / BK;

    const int lane = tid & 31, wid = tid >> 5;
    const int wm = (wid & 3) * 32;
    const int wn = (wid >> 2) * 64;

    float acc[2][8][4];
#pragma unroll
    for (int mt = 0; mt < 2; mt++)
#pragma unroll
        for (int nt = 0; nt < 8; nt++)
#pragma unroll
            for (int j = 0; j < 4; j++) acc[mt][nt][j] = 0.0f;

    auto load_chunk = [&](int c, int s) {
        const __half* Ak = A + (size_t)bm * lda + c * BK;
        const __half* Bk = Bt + (size_t)bn * K + c * BK;
        const uint32_t aOff = sbase + s * STAGE_B;
        const uint32_t bOff = aOff + 16384;
#pragma unroll
        for (int i = 0; i < 4; i++) {
            int u = tid + 256 * i;
            int row = u >> 3, c8 = u & 7;
            uint32_t d = aOff + (uint32_t)(row * 8 + (c8 ^ (row & 7))) * 16;
            CP_ASYNC16(d, Ak + (size_t)row * lda + c8 * 8);
        }
#pragma unroll
        for (int i = 0; i < 4; i++) {
            int u = tid + 256 * i;
            int row = u >> 3, c8 = u & 7;
            uint32_t d = bOff + (uint32_t)(row * 8 + (c8 ^ (row & 7))) * 16;
            CP_ASYNC16(d, Bk + (size_t)row * K + c8 * 8);
        }
    };

    load_chunk(0, 0); CP_COMMIT();
    load_chunk(1, 1); CP_COMMIT();

    int s = 0;
    for (int c = 0; c < NC; c++) {
        if (c + 2 < NC) {
            int s2 = s + 2; if (s2 >= NSTAGE) s2 -= NSTAGE;
            load_chunk(c + 2, s2);
        }
        CP_COMMIT();
        CP_WAIT2();
        __syncthreads();

        const uint32_t aOff = sbase + s * STAGE_B;
        const uint32_t bOff = aOff + 16384;
#pragma unroll
        for (int ks = 0; ks < 4; ks++) {
            uint32_t a[2][4];
#pragma unroll
            for (int mt = 0; mt < 2; mt++) {
                int row = wm + mt * 16 + (lane & 15);
                int c8 = ks * 2 + (lane >> 4);
                uint32_t addr = aOff + (uint32_t)((row * 8 + (c8 ^ (row & 7))) << 4);
                LDSM4(a[mt][0], a[mt][1], a[mt][2], a[mt][3], addr);
            }
            uint32_t b[8][2];
#pragma unroll
            for (int g = 0; g < 4; g++) {
                int row = wn + g * 16 + (lane & 7) + ((lane & 16) >> 1);
                int c8 = ks * 2 + ((lane >> 3) & 1);
                uint32_t addr = bOff + (uint32_t)((row * 8 + (c8 ^ (row & 7))) << 4);
                LDSM4(b[2 * g][0], b[2 * g][1], b[2 * g + 1][0], b[2 * g + 1][1], addr);
            }
#pragma unroll
            for (int mt = 0; mt < 2; mt++)
#pragma unroll
                for (int nt = 0; nt < 8; nt++)
                    MMA_F16(acc[mt][nt], a[mt], b[nt]);
        }
        __syncthreads();
        if (++s >= NSTAGE) s = 0;
    }

#pragma unroll
    for (int mt = 0; mt < 2; mt++) {
        int row0 = bm + wm + mt * 16 + (lane >> 2);
#pragma unroll
        for (int nt = 0; nt < 8; nt++) {
            int col = bn + wn + nt * 8 + (lane & 3) * 2;
            float v0 = acc[mt][nt][0] * alpha, v1 = acc[mt][nt][1] * alpha;
            float v2 = acc[mt][nt][2] * alpha, v3 = acc[mt][nt][3] * alpha;
            if (bias) {
                float b0 = bias[col], b1 = bias[col + 1];
                v0 += b0; v1 += b1; v2 += b0; v3 += b1;
            }
            OT* p0 = C + (size_t)row0 * CH + col;
            OT* p1 = C + (size_t)(row0 + 8) * CH + col;
            if (sizeof(OT) == 2) {
                *(__half2*)p0 = __floats2half2_rn(v0, v1);
                *(__half2*)p1 = __floats2half2_rn(v2, v3);
            } else {
                *(float2*)p0 = make_float2(v0, v1);
                *(float2*)p1 = make_float2(v2, v3);
            }
        }
    }
}

// ---------------------------------------------------------------------------
// Tensor-core attention: one block (128 thr, 4 warps) per (b, h).
// QK^T and PV via m16n8k16; softmax in registers (quad shfl).
// Q pre-scaled by 1/sqrt(hd) in its GEMM epilogue.
// ---------------------------------------------------------------------------
__global__ __launch_bounds__(128) void attn_kernel(
    const __half* __restrict__ Q, const __half* __restrict__ K,
    const __half* __restrict__ V, const __half* __restrict__ B64,
    __half* __restrict__ CTX)
{
    __shared__ __align__(16) __half qs[64 * 64];    // [tok], 8-unit rows, swizzled
    __shared__ __align__(16) __half ksm[64 * 64];
    __shared__ __align__(16) __half vt[32 * 64];    // [d][tok], swizzled
    __shared__ __align__(16) __half sb[64 * 72];    // bias, padded rows

    const int tid = threadIdx.x;
    const int lane = tid & 31, w = tid >> 5;
    const int b = blockIdx.x >> 4, h = blockIdx.x & 15;
    const size_t base = (size_t)b * SEQ * CH + h * HDIM;

    // Load Q, K (swizzled), V (transposed), bias slice
    {
        int tok = tid >> 1;
        int u0 = (tid & 1) * 2;           // first 8-half unit: 0 or 2
        int sw = tok & 7;
        const uint4* qsrc = (const uint4*)(Q + base + (size_t)tok * CH + u0 * 8);
        const uint4* ksrc = (const uint4*)(K + base + (size_t)tok * CH + u0 * 8);
        ((uint4*)qs)[tok * 8 + (u0 ^ sw)]       = qsrc[0];
        ((uint4*)qs)[tok * 8 + ((u0 + 1) ^ sw)] = qsrc[1];
        ((uint4*)ksm)[tok * 8 + (u0 ^ sw)]       = ksrc[0];
        ((uint4*)ksm)[tok * 8 + ((u0 + 1) ^ sw)] = ksrc[1];

        const uint4* vsrc = (const uint4*)(V + base + (size_t)tok * CH + u0 * 8);
        __half vh[16];
        *(uint4*)&vh[0] = vsrc[0];
        *(uint4*)&vh[8] = vsrc[1];
#pragma unroll
        for (int j = 0; j < 16; j++) {
            int d = u0 * 8 + j;
            vt[(d * 8 + ((tok >> 3) ^ (d & 7))) * 8 + (tok & 7)] = vh[j];
        }

        const uint4* bsrc = (const uint4*)(B64 + (size_t)h * 4096);
#pragma unroll
        for (int j = 0; j < 4; j++) {
            uint4 bv = bsrc[tid * 4 + j];
            int row = tid >> 1, col = (tid & 1) * 32 + j * 8;
            *(uint4*)&sb[row * 72 + col] = bv;
        }
    }
    __syncthreads();

    const uint32_t smq = smem_u32(qs), smk = smem_u32(ksm), smv = smem_u32(vt);

    // QK^T: warp w owns score rows 16w..16w+15
    float c[8][4];
#pragma unroll
    for (int nt = 0; nt < 8; nt++)
#pragma unroll
        for (int j = 0; j < 4; j++) c[nt][j] = 0.0f;

    uint32_t aq[2][4];
#pragma unroll
    for (int ks = 0; ks < 2; ks++) {
        int row = 16 * w + (lane & 15);
        int c8 = ks * 2 + (lane >> 4);
        uint32_t addr = smq + ((row * 8 + (c8 ^ (row & 7))) << 4);
        LDSM4(aq[ks][0], aq[ks][1], aq[ks][2], aq[ks][3], addr);
    }
#pragma unroll
    for (int g = 0; g < 4; g++) {
#pragma unroll
        for (int ks = 0; ks < 2; ks++) {
            uint32_t bk0[2], bk1[2];
            int row = 16 * g + (lane & 7) + ((lane & 16) >> 1);
            int c8 = ks * 2 + ((lane >> 3) & 1);
            uint32_t addr = smk + ((row * 8 + (c8 ^ (row & 7))) << 4);
            LDSM4(bk0[0], bk0[1], bk1[0], bk1[1], addr);
            MMA_F16(c[2 * g],     aq[ks], bk0);
            MMA_F16(c[2 * g + 1], aq[ks], bk1);
        }
    }

    // Bias add
    const int r0 = 16 * w + (lane >> 2);
#pragma unroll
    for (int nt = 0; nt < 8; nt++) {
        int col = nt * 8 + (lane & 3) * 2;
        float2 f0 = __half22float2(*(__half2*)&sb[r0 * 72 + col]);
        float2 f1 = __half22float2(*(__half2*)&sb[(r0 + 8) * 72 + col]);
        c[nt][0] += f0.x; c[nt][1] += f0.y;
        c[nt][2] += f1.x; c[nt][3] += f1.y;
    }

    // Softmax over rows r0 and r0+8 (each row spread over a quad of lanes)
    float mx0 = -1e30f, mx1 = -1e30f;
#pragma unroll
    for (int nt = 0; nt < 8; nt++) {
        mx0 = fmaxf(mx0, fmaxf(c[nt][0], c[nt][1]));
        mx1 = fmaxf(mx1, fmaxf(c[nt][2], c[nt][3]));
    }
    mx0 = fmaxf(mx0, __shfl_xor_sync(0xffffffffu, mx0, 1));
    mx0 = fmaxf(mx0, __shfl_xor_sync(0xffffffffu, mx0, 2));
    mx1 = fmaxf(mx1, __shfl_xor_sync(0xffffffffu, mx1, 1));
    mx1 = fmaxf(mx1, __shfl_xor_sync(0xffffffffu, mx1, 2));

    float sum0 = 0.0f, sum1 = 0.0f;
#pragma unroll
    for (int nt = 0; nt < 8; nt++) {
        c[nt][0] = __expf(c[nt][0] - mx0); sum0 += c[nt][0];
        c[nt][1] = __expf(c[nt][1] - mx0); sum0 += c[nt][1];
        c[nt][2] = __expf(c[nt][2] - mx1); sum1 += c[nt][2];
        c[nt][3] = __expf(c[nt][3] - mx1); sum1 += c[nt][3];
    }
    sum0 += __shfl_xor_sync(0xffffffffu, sum0, 1);
    sum0 += __shfl_xor_sync(0xffffffffu, sum0, 2);
    sum1 += __shfl_xor_sync(0xffffffffu, sum1, 1);
    sum1 += __shfl_xor_sync(0xffffffffu, sum1, 2);
    float inv0 = 1.0f / sum0, inv1 = 1.0f / sum1;

    // Convert P to A-frags for PV (c-frag -> a-frag identity)
    uint32_t ap[4][4];
#pragma unroll
    for (int ks = 0; ks < 4; ks++) {
        __half2 t0 = __floats2half2_rn(c[2 * ks][0] * inv0, c[2 * ks][1] * inv0);
        __half2 t1 = __floats2half2_rn(c[2 * ks][2] * inv1, c[2 * ks][3] * inv1);
        __half2 t2 = __floats2half2_rn(c[2 * ks + 1][0] * inv0, c[2 * ks + 1][1] * inv0);
        __half2 t3 = __floats2half2_rn(c[2 * ks + 1][2] * inv1, c[2 * ks + 1][3] * inv1);
        ap[ks][0] = *(uint32_t*)&t0;
        ap[ks][1] = *(uint32_t*)&t1;
        ap[ks][2] = *(uint32_t*)&t2;
        ap[ks][3] = *(uint32_t*)&t3;
    }

    // PV: output 16x32 per warp
    float o[4][4];
#pragma unroll
    for (int nt = 0; nt < 4; nt++)
#pragma unroll
        for (int j = 0; j < 4; j++) o[nt][j] = 0.0f;
#pragma unroll
    for (int g = 0; g < 2; g++) {
#pragma unroll
        for (int ks = 0; ks < 4; ks++) {
            uint32_t bv0[2], bv1[2];
            int row = 16 * g + (lane & 7) + ((lane & 16) >> 1);
            int c8 = ks * 2 + ((lane >> 3) & 1);
            uint32_t addr = smv + ((row * 8 + (c8 ^ (row & 7))) << 4);
            LDSM4(bv0[0], bv0[1], bv1[0], bv1[1], addr);
            MMA_F16(o[2 * g],     ap[ks], bv0);
            MMA_F16(o[2 * g + 1], ap[ks], bv1);
        }
    }

    // Write CTX (half)
#pragma unroll
    for (int nt = 0; nt < 4; nt++) {
        int col = nt * 8 + (lane & 3) * 2;
        *(__half2*)(CTX + base + (size_t)r0 * CH + col) =
            __floats2half2_rn(o[nt][0], o[nt][1]);
        *(__half2*)(CTX + base + (size_t)(r0 + 8) * CH + col) =
            __floats2half2_rn(o[nt][2], o[nt][3]);
    }
}

// ---------------------------------------------------------------------------
// Launch
// ---------------------------------------------------------------------------
extern "C" void kernel_launch(void* const* d_in, const int* in_sizes, int n_in,
                              void* d_out, int out_size) {
    const float* x          = (const float*)d_in[0];
    const float* Wq         = (const float*)d_in[1];
    const float* Wk_base    = (const float*)d_in[2];
    const float* Wk_spline  = (const float*)d_in[3];
    const float* Wv         = (const float*)d_in[4];
    const float* Wproj      = (const float*)d_in[5];
    const float* bproj      = (const float*)d_in[6];
    const float* bias_table = (const float*)d_in[7];
    float* out = (float*)d_out;

    __half *XA, *XR, *Qp, *Kp, *Vp, *CTX, *WqT, *WvT, *WpT, *WkT, *B64;
    cudaGetSymbolAddress((void**)&XA,  g_XA);
    cudaGetSymbolAddress((void**)&XR,  g_XR);
    cudaGetSymbolAddress((void**)&Qp,  g_Q);
    cudaGetSymbolAddress((void**)&Kp,  g_K);
    cudaGetSymbolAddress((void**)&Vp,  g_V);
    cudaGetSymbolAddress((void**)&CTX, g_CTX);
    cudaGetSymbolAddress((void**)&WqT, g_WqT);
    cudaGetSymbolAddress((void**)&WvT, g_WvT);
    cudaGetSymbolAddress((void**)&WpT, g_WpT);
    cudaGetSymbolAddress((void**)&WkT, g_WkT);
    cudaGetSymbolAddress((void**)&B64, g_B64);

    cudaFuncSetAttribute(gemm_f16_kernel<__half>,
                         cudaFuncAttributeMaxDynamicSharedMemorySize, SMEM_TOT);
    cudaFuncSetAttribute(gemm_f16_kernel<float>,
                         cudaFuncAttributeMaxDynamicSharedMemorySize, SMEM_TOT);

    const float scale = 0.17677669529663687f;  // 1/sqrt(32)
    dim3 gg(CH / 128, MROWS / 128);            // (4, 256)

    // Order chosen so the ncu bounded capture lands on the K-GEMM.
    build_wkt_kernel<<<(CH * XAW + 255) / 256, 256>>>(Wk_base, Wk_spline, WkT);
    prep_kernel<<<(MROWS * CH + 255) / 256, 256>>>(x, XA, XR);
    trans512_kernel<<<(CH * CH + 255) / 256, 256>>>(Wq, WqT);

    gemm_f16_kernel<__half><<<gg, 256, SMEM_TOT>>>(XA, XAW, WkT, XAW, Kp, nullptr, 1.0f);

    trans512_kernel<<<(CH * CH + 255) / 256, 256>>>(Wv, WvT);
    trans512_kernel<<<(CH * CH + 255) / 256, 256>>>(Wproj, WpT);
    build_b64_kernel<<<(HEADS * SEQ * SEQ + 255) / 256, 256>>>(bias_table, B64);

    gemm_f16_kernel<__half><<<gg, 256, SMEM_TOT>>>(XR, CH, WqT, CH, Qp, nullptr, scale);
    gemm_f16_kernel<__half><<<gg, 256, SMEM_TOT>>>(XR, CH, WvT, CH, Vp, nullptr, 1.0f);

    attn_kernel<<<BATCH * HEADS, 128>>>(Qp, Kp, Vp, B64, CTX);

    gemm_f16_kernel<float><<<gg, 256, SMEM_TOT>>>(CTX, CH, WpT, CH, out, bproj, 1.0f);
}

// round 7
// speedup vs baseline: 9.5802x; 1.0120x over previous
#include <cuda_runtime.h>
#include <cuda_fp16.h>
#include <cstdint>

// Problem constants
#define BATCH   512
#define SEQ     64
#define CH      512
#define HEADS   16
#define HDIM    32
#define GRIDN   5
#define MROWS   (BATCH * SEQ)          // 32768
#define XAW     (CH * (GRIDN + 1))     // 3072: [swish | phi0 | ... | phi4]

// Scratch (device globals — no allocation allowed)
__device__ __align__(16) __half g_XA[(size_t)MROWS * XAW];
__device__ __align__(16) __half g_XR[(size_t)MROWS * CH];
__device__ __align__(16) __half g_Q[(size_t)MROWS * CH];
__device__ __align__(16) __half g_K[(size_t)MROWS * CH];
__device__ __align__(16) __half g_V[(size_t)MROWS * CH];
__device__ __align__(16) __half g_CTX[(size_t)MROWS * CH];
__device__ __align__(16) __half g_WqT[CH * CH];          // [n][k]
__device__ __align__(16) __half g_WvT[CH * CH];
__device__ __align__(16) __half g_WpT[CH * CH];
__device__ __align__(16) __half g_WkT[(size_t)CH * XAW]; // [n][3072]
__device__ __align__(16) __half g_B64[HEADS * SEQ * SEQ]; // per-head bias [h][n][m]

// ---------------------------------------------------------------------------
// PTX helpers
// ---------------------------------------------------------------------------
__device__ __forceinline__ uint32_t smem_u32(const void* p) {
    uint32_t a;
    asm("{ .reg .u64 t; cvta.to.shared.u64 t, %1; cvt.u32.u64 %0, t; }" : "=r"(a) : "l"(p));
    return a;
}
#define CP_ASYNC16(dst, src) \
    asm volatile("cp.async.cg.shared.global [%0], [%1], 16;" :: "r"(dst), "l"(src))
#define CP_COMMIT() asm volatile("cp.async.commit_group;" ::: "memory")
#define CP_WAIT2()  asm volatile("cp.async.wait_group 2;" ::: "memory")

#define LDSM4(r0, r1, r2, r3, addr) \
    asm volatile("ldmatrix.sync.aligned.m8n8.x4.shared.b16 {%0,%1,%2,%3}, [%4];" \
                 : "=r"(r0), "=r"(r1), "=r"(r2), "=r"(r3) : "r"(addr))

#define MMA_F16(d, a, b) \
    asm volatile("mma.sync.aligned.m16n8k16.row.col.f32.f16.f16.f32 " \
                 "{%0,%1,%2,%3}, {%4,%5,%6,%7}, {%8,%9}, {%0,%1,%2,%3};" \
                 : "+f"((d)[0]), "+f"((d)[1]), "+f"((d)[2]), "+f"((d)[3]) \
                 : "r"((a)[0]), "r"((a)[1]), "r"((a)[2]), "r"((a)[3]), \
                   "r"((b)[0]), "r"((b)[1]))

// ---------------------------------------------------------------------------
// Prep: XR = half(x); XA[m,c] = half(swish(x));
//       XA[m, 512 + g*512 + c] = half(exp(-(x-(g-2))^2))
// ---------------------------------------------------------------------------
__global__ __launch_bounds__(256) void prep_kernel(const float* __restrict__ x,
                                                   __half* __restrict__ XA,
                                                   __half* __restrict__ XR) {
    int idx = blockIdx.x * blockDim.x + threadIdx.x;
    if (idx >= MROWS * CH) return;
    int m = idx >> 9;
    int c = idx & 511;
    float v = x[idx];
    XR[idx] = __float2half_rn(v);
    __half* row = XA + (size_t)m * XAW;
    row[c] = __float2half_rn(v / (1.0f + __expf(-v)));
#pragma unroll
    for (int g = 0; g < GRIDN; g++) {
        float d = v - (float)(g - 2);
        row[CH + g * CH + c] = __float2half_rn(__expf(-d * d));
    }
}

// ---------------------------------------------------------------------------
// Weight transposes: WT[n,k] = half(W[k,n])
// ---------------------------------------------------------------------------
__global__ __launch_bounds__(256) void trans512_kernel(const float* __restrict__ W,
                                                       __half* __restrict__ WT) {
    int idx = blockIdx.x * blockDim.x + threadIdx.x;
    if (idx >= CH * CH) return;
    int n = idx >> 9;
    int k = idx & 511;
    WT[idx] = __float2half_rn(W[k * CH + n]);
}

// WkT[n][k]: k<512 -> Wk_base[k][n]; k=512+g*512+c -> Wk_spline[c*5+g][n]
__global__ __launch_bounds__(256) void build_wkt_kernel(const float* __restrict__ Wb,
                                                        const float* __restrict__ Ws,
                                                        __half* __restrict__ WkT) {
    int idx = blockIdx.x * blockDim.x + threadIdx.x;
    if (idx >= CH * XAW) return;
    int n = idx / XAW;
    int k = idx - n * XAW;
    float v;
    if (k < CH) {
        v = Wb[k * CH + n];
    } else {
        int kk = k - CH;
        int g = kk >> 9;
        int c = kk & 511;
        v = Ws[(c * GRIDN + g) * CH + n];
    }
    WkT[idx] = __float2half_rn(v);
}

// Per-head relative-position bias table: B64[h][n][m] (half)
__global__ __launch_bounds__(256) void build_b64_kernel(const float* __restrict__ bt,
                                                        __half* __restrict__ B64) {
    int idx = blockIdx.x * blockDim.x + threadIdx.x;
    if (idx >= HEADS * SEQ * SEQ) return;
    int h = idx >> 12;
    int nm = idx & 4095;
    int n = nm >> 6, m = nm & 63;
    int i1 = n >> 3, j1 = n & 7;
    int i2 = m >> 3, j2 = m & 7;
    int ridx = (i1 - i2 + 7) * 15 + (j1 - j2 + 7);
    B64[idx] = __float2half_rn(bt[ridx * HEADS + h]);
}

// ---------------------------------------------------------------------------
// fp16 mma.sync GEMM: C[M, 512] = alpha * A[M, K](f16) @ Bt[512, K](f16)^T (+bias)
// Output type templated (half for Q/K/V, float for proj).
// BM=BN=128, BK=64; 8 warps (4x2), warp tile 32x64; 3-stage cp.async.
// ---------------------------------------------------------------------------
#define BK        64
#define STAGE_B   32768                 // A 16KB + B 16KB
#define NSTAGE    3
#define SMEM_TOT  (NSTAGE * STAGE_B)    // 98304

template <typename OT>
__global__ __launch_bounds__(256, 2) void gemm_f16_kernel(
    const __half* __restrict__ A, int lda,
    const __half* __restrict__ Bt, int K,
    OT* __restrict__ C,
    const float* __restrict__ bias, float alpha)
{
    extern __shared__ __align__(16) char smc[];
    const uint32_t sbase = smem_u32(smc);
    const int tid = threadIdx.x;
    const int bm = blockIdx.y * 128;
    const int bn = blockIdx.x * 128;
    const int NC = K / BK;

    const int lane = tid & 31, wid = tid >> 5;
    const int wm = (wid & 3) * 32;
    const int wn = (wid >> 2) * 64;

    float acc[2][8][4];
#pragma unroll
    for (int mt = 0; mt < 2; mt++)
#pragma unroll
        for (int nt = 0; nt < 8; nt++)
#pragma unroll
            for (int j = 0; j < 4; j++) acc[mt][nt][j] = 0.0f;

    auto load_chunk = [&](int c, int s) {
        const __half* Ak = A + (size_t)bm * lda + c * BK;
        const __half* Bk = Bt + (size_t)bn * K + c * BK;
        const uint32_t aOff = sbase + s * STAGE_B;
        const uint32_t bOff = aOff + 16384;
#pragma unroll
        for (int i = 0; i < 4; i++) {
            int u = tid + 256 * i;
            int row = u >> 3, c8 = u & 7;
            uint32_t d = aOff + (uint32_t)(row * 8 + (c8 ^ (row & 7))) * 16;
            CP_ASYNC16(d, Ak + (size_t)row * lda + c8 * 8);
        }
#pragma unroll
        for (int i = 0; i < 4; i++) {
            int u = tid + 256 * i;
            int row = u >> 3, c8 = u & 7;
            uint32_t d = bOff + (uint32_t)(row * 8 + (c8 ^ (row & 7))) * 16;
            CP_ASYNC16(d, Bk + (size_t)row * K + c8 * 8);
        }
    };

    load_chunk(0, 0); CP_COMMIT();
    load_chunk(1, 1); CP_COMMIT();

    int s = 0;
    for (int c = 0; c < NC; c++) {
        if (c + 2 < NC) {
            int s2 = s + 2; if (s2 >= NSTAGE) s2 -= NSTAGE;
            load_chunk(c + 2, s2);
        }
        CP_COMMIT();
        CP_WAIT2();
        __syncthreads();

        const uint32_t aOff = sbase + s * STAGE_B;
        const uint32_t bOff = aOff + 16384;
#pragma unroll
        for (int ks = 0; ks < 4; ks++) {
            uint32_t a[2][4];
#pragma unroll
            for (int mt = 0; mt < 2; mt++) {
                int row = wm + mt * 16 + (lane & 15);
                int c8 = ks * 2 + (lane >> 4);
                uint32_t addr = aOff + (uint32_t)((row * 8 + (c8 ^ (row & 7))) << 4);
                LDSM4(a[mt][0], a[mt][1], a[mt][2], a[mt][3], addr);
            }
            uint32_t b[8][2];
#pragma unroll
            for (int g = 0; g < 4; g++) {
                int row = wn + g * 16 + (lane & 7) + ((lane & 16) >> 1);
                int c8 = ks * 2 + ((lane >> 3) & 1);
                uint32_t addr = bOff + (uint32_t)((row * 8 + (c8 ^ (row & 7))) << 4);
                LDSM4(b[2 * g][0], b[2 * g][1], b[2 * g + 1][0], b[2 * g + 1][1], addr);
            }
#pragma unroll
            for (int mt = 0; mt < 2; mt++)
#pragma unroll
                for (int nt = 0; nt < 8; nt++)
                    MMA_F16(acc[mt][nt], a[mt], b[nt]);
        }
        __syncthreads();
        if (++s >= NSTAGE) s = 0;
    }

#pragma unroll
    for (int mt = 0; mt < 2; mt++) {
        int row0 = bm + wm + mt * 16 + (lane >> 2);
#pragma unroll
        for (int nt = 0; nt < 8; nt++) {
            int col = bn + wn + nt * 8 + (lane & 3) * 2;
            float v0 = acc[mt][nt][0] * alpha, v1 = acc[mt][nt][1] * alpha;
            float v2 = acc[mt][nt][2] * alpha, v3 = acc[mt][nt][3] * alpha;
            if (bias) {
                float b0 = bias[col], b1 = bias[col + 1];
                v0 += b0; v1 += b1; v2 += b0; v3 += b1;
            }
            OT* p0 = C + (size_t)row0 * CH + col;
            OT* p1 = C + (size_t)(row0 + 8) * CH + col;
            if (sizeof(OT) == 2) {
                *(__half2*)p0 = __floats2half2_rn(v0, v1);
                *(__half2*)p1 = __floats2half2_rn(v2, v3);
            } else {
                *(float2*)p0 = make_float2(v0, v1);
                *(float2*)p1 = make_float2(v2, v3);
            }
        }
    }
}

// ---------------------------------------------------------------------------
// Tensor-core attention: one block (128 thr, 4 warps) per (b, h).
// QK^T and PV via m16n8k16; softmax in registers (quad shfl).
// Q pre-scaled by 1/sqrt(hd) in its GEMM epilogue.
// ---------------------------------------------------------------------------
__global__ __launch_bounds__(128) void attn_kernel(
    const __half* __restrict__ Q, const __half* __restrict__ K,
    const __half* __restrict__ V, const __half* __restrict__ B64,
    __half* __restrict__ CTX)
{
    __shared__ __align__(16) __half qs[64 * 64];    // [tok], 8-unit rows, swizzled
    __shared__ __align__(16) __half ksm[64 * 64];
    __shared__ __align__(16) __half vt[32 * 64];    // [d][tok], swizzled
    __shared__ __align__(16) __half sb[64 * 72];    // bias, padded rows

    const int tid = threadIdx.x;
    const int lane = tid & 31, w = tid >> 5;
    const int b = blockIdx.x >> 4, h = blockIdx.x & 15;
    const size_t base = (size_t)b * SEQ * CH + h * HDIM;

    // Load Q, K (swizzled), V (transposed), bias slice
    {
        int tok = tid >> 1;
        int u0 = (tid & 1) * 2;           // first 8-half unit: 0 or 2
        int sw = tok & 7;
        const uint4* qsrc = (const uint4*)(Q + base + (size_t)tok * CH + u0 * 8);
        const uint4* ksrc = (const uint4*)(K + base + (size_t)tok * CH + u0 * 8);
        ((uint4*)qs)[tok * 8 + (u0 ^ sw)]       = qsrc[0];
        ((uint4*)qs)[tok * 8 + ((u0 + 1) ^ sw)] = qsrc[1];
        ((uint4*)ksm)[tok * 8 + (u0 ^ sw)]       = ksrc[0];
        ((uint4*)ksm)[tok * 8 + ((u0 + 1) ^ sw)] = ksrc[1];

        const uint4* vsrc = (const uint4*)(V + base + (size_t)tok * CH + u0 * 8);
        __half vh[16];
        *(uint4*)&vh[0] = vsrc[0];
        *(uint4*)&vh[8] = vsrc[1];
#pragma unroll
        for (int j = 0; j < 16; j++) {
            int d = u0 * 8 + j;
            vt[(d * 8 + ((tok >> 3) ^ (d & 7))) * 8 + (tok & 7)] = vh[j];
        }

        const uint4* bsrc = (const uint4*)(B64 + (size_t)h * 4096);
#pragma unroll
        for (int j = 0; j < 4; j++) {
            uint4 bv = bsrc[tid * 4 + j];
            int row = tid >> 1, col = (tid & 1) * 32 + j * 8;
            *(uint4*)&sb[row * 72 + col] = bv;
        }
    }
    __syncthreads();

    const uint32_t smq = smem_u32(qs), smk = smem_u32(ksm), smv = smem_u32(vt);

    // QK^T: warp w owns score rows 16w..16w+15
    float c[8][4];
#pragma unroll
    for (int nt = 0; nt < 8; nt++)
#pragma unroll
        for (int j = 0; j < 4; j++) c[nt][j] = 0.0f;

    uint32_t aq[2][4];
#pragma unroll
    for (int ks = 0; ks < 2; ks++) {
        int row = 16 * w + (lane & 15);
        int c8 = ks * 2 + (lane >> 4);
        uint32_t addr = smq + ((row * 8 + (c8 ^ (row & 7))) << 4);
        LDSM4(aq[ks][0], aq[ks][1], aq[ks][2], aq[ks][3], addr);
    }
#pragma unroll
    for (int g = 0; g < 4; g++) {
#pragma unroll
        for (int ks = 0; ks < 2; ks++) {
            uint32_t bk0[2], bk1[2];
            int row = 16 * g + (lane & 7) + ((lane & 16) >> 1);
            int c8 = ks * 2 + ((lane >> 3) & 1);
            uint32_t addr = smk + ((row * 8 + (c8 ^ (row & 7))) << 4);
            LDSM4(bk0[0], bk0[1], bk1[0], bk1[1], addr);
            MMA_F16(c[2 * g],     aq[ks], bk0);
            MMA_F16(c[2 * g + 1], aq[ks], bk1);
        }
    }

    // Bias add
    const int r0 = 16 * w + (lane >> 2);
#pragma unroll
    for (int nt = 0; nt < 8; nt++) {
        int col = nt * 8 + (lane & 3) * 2;
        float2 f0 = __half22float2(*(__half2*)&sb[r0 * 72 + col]);
        float2 f1 = __half22float2(*(__half2*)&sb[(r0 + 8) * 72 + col]);
        c[nt][0] += f0.x; c[nt][1] += f0.y;
        c[nt][2] += f1.x; c[nt][3] += f1.y;
    }

    // Softmax over rows r0 and r0+8 (each row spread over a quad of lanes)
    float mx0 = -1e30f, mx1 = -1e30f;
#pragma unroll
    for (int nt = 0; nt < 8; nt++) {
        mx0 = fmaxf(mx0, fmaxf(c[nt][0], c[nt][1]));
        mx1 = fmaxf(mx1, fmaxf(c[nt][2], c[nt][3]));
    }
    mx0 = fmaxf(mx0, __shfl_xor_sync(0xffffffffu, mx0, 1));
    mx0 = fmaxf(mx0, __shfl_xor_sync(0xffffffffu, mx0, 2));
    mx1 = fmaxf(mx1, __shfl_xor_sync(0xffffffffu, mx1, 1));
    mx1 = fmaxf(mx1, __shfl_xor_sync(0xffffffffu, mx1, 2));

    float sum0 = 0.0f, sum1 = 0.0f;
#pragma unroll
    for (int nt = 0; nt < 8; nt++) {
        c[nt][0] = __expf(c[nt][0] - mx0); sum0 += c[nt][0];
        c[nt][1] = __expf(c[nt][1] - mx0); sum0 += c[nt][1];
        c[nt][2] = __expf(c[nt][2] - mx1); sum1 += c[nt][2];
        c[nt][3] = __expf(c[nt][3] - mx1); sum1 += c[nt][3];
    }
    sum0 += __shfl_xor_sync(0xffffffffu, sum0, 1);
    sum0 += __shfl_xor_sync(0xffffffffu, sum0, 2);
    sum1 += __shfl_xor_sync(0xffffffffu, sum1, 1);
    sum1 += __shfl_xor_sync(0xffffffffu, sum1, 2);
    float inv0 = 1.0f / sum0, inv1 = 1.0f / sum1;

    // Convert P to A-frags for PV (c-frag -> a-frag identity)
    uint32_t ap[4][4];
#pragma unroll
    for (int ks = 0; ks < 4; ks++) {
        __half2 t0 = __floats2half2_rn(c[2 * ks][0] * inv0, c[2 * ks][1] * inv0);
        __half2 t1 = __floats2half2_rn(c[2 * ks][2] * inv1, c[2 * ks][3] * inv1);
        __half2 t2 = __floats2half2_rn(c[2 * ks + 1][0] * inv0, c[2 * ks + 1][1] * inv0);
        __half2 t3 = __floats2half2_rn(c[2 * ks + 1][2] * inv1, c[2 * ks + 1][3] * inv1);
        ap[ks][0] = *(uint32_t*)&t0;
        ap[ks][1] = *(uint32_t*)&t1;
        ap[ks][2] = *(uint32_t*)&t2;
        ap[ks][3] = *(uint32_t*)&t3;
    }

    // PV: output 16x32 per warp
    float o[4][4];
#pragma unroll
    for (int nt = 0; nt < 4; nt++)
#pragma unroll
        for (int j = 0; j < 4; j++) o[nt][j] = 0.0f;
#pragma unroll
    for (int g = 0; g < 2; g++) {
#pragma unroll
        for (int ks = 0; ks < 4; ks++) {
            uint32_t bv0[2], bv1[2];
            int row = 16 * g + (lane & 7) + ((lane & 16) >> 1);
            int c8 = ks * 2 + ((lane >> 3) & 1);
            uint32_t addr = smv + ((row * 8 + (c8 ^ (row & 7))) << 4);
            LDSM4(bv0[0], bv0[1], bv1[0], bv1[1], addr);
            MMA_F16(o[2 * g],     ap[ks], bv0);
            MMA_F16(o[2 * g + 1], ap[ks], bv1);
        }
    }

    // Write CTX (half)
#pragma unroll
    for (int nt = 0; nt < 4; nt++) {
        int col = nt * 8 + (lane & 3) * 2;
        *(__half2*)(CTX + base + (size_t)r0 * CH + col) =
            __floats2half2_rn(o[nt][0], o[nt][1]);
        *(__half2*)(CTX + base + (size_t)(r0 + 8) * CH + col) =
            __floats2half2_rn(o[nt][2], o[nt][3]);
    }
}

// ---------------------------------------------------------------------------
// Launch
// ---------------------------------------------------------------------------
extern "C" void kernel_launch(void* const* d_in, const int* in_sizes, int n_in,
                              void* d_out, int out_size) {
    const float* x          = (const float*)d_in[0];
    const float* Wq         = (const float*)d_in[1];
    const float* Wk_base    = (const float*)d_in[2];
    const float* Wk_spline  = (const float*)d_in[3];
    const float* Wv         = (const float*)d_in[4];
    const float* Wproj      = (const float*)d_in[5];
    const float* bproj      = (const float*)d_in[6];
    const float* bias_table = (const float*)d_in[7];
    float* out = (float*)d_out;

    __half *XA, *XR, *Qp, *Kp, *Vp, *CTX, *WqT, *WvT, *WpT, *WkT, *B64;
    cudaGetSymbolAddress((void**)&XA,  g_XA);
    cudaGetSymbolAddress((void**)&XR,  g_XR);
    cudaGetSymbolAddress((void**)&Qp,  g_Q);
    cudaGetSymbolAddress((void**)&Kp,  g_K);
    cudaGetSymbolAddress((void**)&Vp,  g_V);
    cudaGetSymbolAddress((void**)&CTX, g_CTX);
    cudaGetSymbolAddress((void**)&WqT, g_WqT);
    cudaGetSymbolAddress((void**)&WvT, g_WvT);
    cudaGetSymbolAddress((void**)&WpT, g_WpT);
    cudaGetSymbolAddress((void**)&WkT, g_WkT);
    cudaGetSymbolAddress((void**)&B64, g_B64);

    cudaFuncSetAttribute(gemm_f16_kernel<__half>,
                         cudaFuncAttributeMaxDynamicSharedMemorySize, SMEM_TOT);
    cudaFuncSetAttribute(gemm_f16_kernel<float>,
                         cudaFuncAttributeMaxDynamicSharedMemorySize, SMEM_TOT);

    const float scale = 0.17677669529663687f;  // 1/sqrt(32)
    dim3 gg(CH / 128, MROWS / 128);            // (4, 256)

    // Order chosen so the ncu bounded capture lands on the K-GEMM.
    build_wkt_kernel<<<(CH * XAW + 255) / 256, 256>>>(Wk_base, Wk_spline, WkT);
    prep_kernel<<<(MROWS * CH + 255) / 256, 256>>>(x, XA, XR);
    trans512_kernel<<<(CH * CH + 255) / 256, 256>>>(Wq, WqT);

    gemm_f16_kernel<__half><<<gg, 256, SMEM_TOT>>>(XA, XAW, WkT, XAW, Kp, nullptr, 1.0f);

    trans512_kernel<<<(CH * CH + 255) / 256, 256>>>(Wv, WvT);
    trans512_kernel<<<(CH * CH + 255) / 256, 256>>>(Wproj, WpT);
    build_b64_kernel<<<(HEADS * SEQ * SEQ + 255) / 256, 256>>>(bias_table, B64);

    gemm_f16_kernel<__half><<<gg, 256, SMEM_TOT>>>(XR, CH, WqT, CH, Qp, nullptr, scale);
    gemm_f16_kernel<__half><<<gg, 256, SMEM_TOT>>>(XR, CH, WvT, CH, Vp, nullptr, 1.0f);

    attn_kernel<<<BATCH * HEADS, 128>>>(Qp, Kp, Vp, B64, CTX);

    gemm_f16_kernel<float><<<gg, 256, SMEM_TOT>>>(CTX, CH, WpT, CH, out, bproj, 1.0f);
}

// round 8
// speedup vs baseline: 9.5819x; 1.0002x over previous
#include <cuda_runtime.h>
#include <cuda_fp16.h>
#include <cstdint>

// Problem constants
#define BATCH   512
#define SEQ     64
#define CH      512
#define HEADS   16
#define HDIM    32
#define GRIDN   5
#define MROWS   (BATCH * SEQ)          // 32768
#define XAW     (CH * (GRIDN + 1))     // 3072: [swish | phi0 | ... | phi4]

// Scratch (device globals — no allocation allowed)
__device__ __align__(16) __half g_XA[(size_t)MROWS * XAW];
__device__ __align__(16) __half g_XR[(size_t)MROWS * CH];
__device__ __align__(16) __half g_Q[(size_t)MROWS * CH];
__device__ __align__(16) __half g_K[(size_t)MROWS * CH];
__device__ __align__(16) __half g_V[(size_t)MROWS * CH];
__device__ __align__(16) __half g_CTX[(size_t)MROWS * CH];
__device__ __align__(16) __half g_WqT[CH * CH];          // [n][k]
__device__ __align__(16) __half g_WvT[CH * CH];
__device__ __align__(16) __half g_WpT[CH * CH];
__device__ __align__(16) __half g_WkT[(size_t)CH * XAW]; // [n][3072]
__device__ __align__(16) __half g_B64[HEADS * SEQ * SEQ]; // per-head bias [h][n][m]

// ---------------------------------------------------------------------------
// PTX helpers
// ---------------------------------------------------------------------------
__device__ __forceinline__ uint32_t smem_u32(const void* p) {
    uint32_t a;
    asm("{ .reg .u64 t; cvta.to.shared.u64 t, %1; cvt.u32.u64 %0, t; }" : "=r"(a) : "l"(p));
    return a;
}
#define CP_ASYNC16(dst, src) \
    asm volatile("cp.async.cg.shared.global [%0], [%1], 16;" :: "r"(dst), "l"(src))
#define CP_COMMIT() asm volatile("cp.async.commit_group;" ::: "memory")
#define CP_WAIT2()  asm volatile("cp.async.wait_group 2;" ::: "memory")

#define LDSM4(r0, r1, r2, r3, addr) \
    asm volatile("ldmatrix.sync.aligned.m8n8.x4.shared.b16 {%0,%1,%2,%3}, [%4];" \
                 : "=r"(r0), "=r"(r1), "=r"(r2), "=r"(r3) : "r"(addr))

#define MMA_F16(d, a, b) \
    asm volatile("mma.sync.aligned.m16n8k16.row.col.f32.f16.f16.f32 " \
                 "{%0,%1,%2,%3}, {%4,%5,%6,%7}, {%8,%9}, {%0,%1,%2,%3};" \
                 : "+f"((d)[0]), "+f"((d)[1]), "+f"((d)[2]), "+f"((d)[3]) \
                 : "r"((a)[0]), "r"((a)[1]), "r"((a)[2]), "r"((a)[3]), \
                   "r"((b)[0]), "r"((b)[1]))

// ---------------------------------------------------------------------------
// Prep: XR = half(x); XA[m,c] = half(swish(x));
//       XA[m, 512 + g*512 + c] = half(exp(-(x-(g-2))^2))
// ---------------------------------------------------------------------------
__global__ __launch_bounds__(256) void prep_kernel(const float* __restrict__ x,
                                                   __half* __restrict__ XA,
                                                   __half* __restrict__ XR) {
    int idx = blockIdx.x * blockDim.x + threadIdx.x;
    if (idx >= MROWS * CH) return;
    int m = idx >> 9;
    int c = idx & 511;
    float v = x[idx];
    XR[idx] = __float2half_rn(v);
    __half* row = XA + (size_t)m * XAW;
    row[c] = __float2half_rn(v / (1.0f + __expf(-v)));
#pragma unroll
    for (int g = 0; g < GRIDN; g++) {
        float d = v - (float)(g - 2);
        row[CH + g * CH + c] = __float2half_rn(__expf(-d * d));
    }
}

// ---------------------------------------------------------------------------
// Weight transposes: WT[n,k] = half(W[k,n])
// ---------------------------------------------------------------------------
__global__ __launch_bounds__(256) void trans512_kernel(const float* __restrict__ W,
                                                       __half* __restrict__ WT) {
    int idx = blockIdx.x * blockDim.x + threadIdx.x;
    if (idx >= CH * CH) return;
    int n = idx >> 9;
    int k = idx & 511;
    WT[idx] = __float2half_rn(W[k * CH + n]);
}

// WkT[n][k]: k<512 -> Wk_base[k][n]; k=512+g*512+c -> Wk_spline[c*5+g][n]
__global__ __launch_bounds__(256) void build_wkt_kernel(const float* __restrict__ Wb,
                                                        const float* __restrict__ Ws,
                                                        __half* __restrict__ WkT) {
    int idx = blockIdx.x * blockDim.x + threadIdx.x;
    if (idx >= CH * XAW) return;
    int n = idx / XAW;
    int k = idx - n * XAW;
    float v;
    if (k < CH) {
        v = Wb[k * CH + n];
    } else {
        int kk = k - CH;
        int g = kk >> 9;
        int c = kk & 511;
        v = Ws[(c * GRIDN + g) * CH + n];
    }
    WkT[idx] = __float2half_rn(v);
}

// Per-head relative-position bias table: B64[h][n][m] (half)
__global__ __launch_bounds__(256) void build_b64_kernel(const float* __restrict__ bt,
                                                        __half* __restrict__ B64) {
    int idx = blockIdx.x * blockDim.x + threadIdx.x;
    if (idx >= HEADS * SEQ * SEQ) return;
    int h = idx >> 12;
    int nm = idx & 4095;
    int n = nm >> 6, m = nm & 63;
    int i1 = n >> 3, j1 = n & 7;
    int i2 = m >> 3, j2 = m & 7;
    int ridx = (i1 - i2 + 7) * 15 + (j1 - j2 + 7);
    B64[idx] = __float2half_rn(bt[ridx * HEADS + h]);
}

// ---------------------------------------------------------------------------
// fp16 mma.sync GEMM: C[M, 512] = alpha * A[M, K](f16) @ Bt[512, K](f16)^T (+bias)
// Output type templated (half for Q/K/V, float for proj).
// BM=BN=128, BK=64; 8 warps (4x2), warp tile 32x64; 3-stage cp.async.
// ---------------------------------------------------------------------------
#define BK        64
#define STAGE_B   32768                 // A 16KB + B 16KB
#define NSTAGE    3
#define SMEM_TOT  (NSTAGE * STAGE_B)    // 98304

template <typename OT>
__global__ __launch_bounds__(256, 2) void gemm_f16_kernel(
    const __half* __restrict__ A, int lda,
    const __half* __restrict__ Bt, int K,
    OT* __restrict__ C,
    const float* __restrict__ bias, float alpha)
{
    extern __shared__ __align__(16) char smc[];
    const uint32_t sbase = smem_u32(smc);
    const int tid = threadIdx.x;
    const int bm = blockIdx.y * 128;
    const int bn = blockIdx.x * 128;
    const int NC = K / BK;

    const int lane = tid & 31, wid = tid >> 5;
    const int wm = (wid & 3) * 32;
    const int wn = (wid >> 2) * 64;

    float acc[2][8][4];
#pragma unroll
    for (int mt = 0; mt < 2; mt++)
#pragma unroll
        for (int nt = 0; nt < 8; nt++)
#pragma unroll
            for (int j = 0; j < 4; j++) acc[mt][nt][j] = 0.0f;

    auto load_chunk = [&](int c, int s) {
        const __half* Ak = A + (size_t)bm * lda + c * BK;
        const __half* Bk = Bt + (size_t)bn * K + c * BK;
        const uint32_t aOff = sbase + s * STAGE_B;
        const uint32_t bOff = aOff + 16384;
#pragma unroll
        for (int i = 0; i < 4; i++) {
            int u = tid + 256 * i;
            int row = u >> 3, c8 = u & 7;
            uint32_t d = aOff + (uint32_t)(row * 8 + (c8 ^ (row & 7))) * 16;
            CP_ASYNC16(d, Ak + (size_t)row * lda + c8 * 8);
        }
#pragma unroll
        for (int i = 0; i < 4; i++) {
            int u = tid + 256 * i;
            int row = u >> 3, c8 = u & 7;
            uint32_t d = bOff + (uint32_t)(row * 8 + (c8 ^ (row & 7))) * 16;
            CP_ASYNC16(d, Bk + (size_t)row * K + c8 * 8);
        }
    };

    load_chunk(0, 0); CP_COMMIT();
    load_chunk(1, 1); CP_COMMIT();

    int s = 0;
    for (int c = 0; c < NC; c++) {
        if (c + 2 < NC) {
            int s2 = s + 2; if (s2 >= NSTAGE) s2 -= NSTAGE;
            load_chunk(c + 2, s2);
        }
        CP_COMMIT();
        CP_WAIT2();
        __syncthreads();

        const uint32_t aOff = sbase + s * STAGE_B;
        const uint32_t bOff = aOff + 16384;
#pragma unroll
        for (int ks = 0; ks < 4; ks++) {
            uint32_t a[2][4];
#pragma unroll
            for (int mt = 0; mt < 2; mt++) {
                int row = wm + mt * 16 + (lane & 15);
                int c8 = ks * 2 + (lane >> 4);
                uint32_t addr = aOff + (uint32_t)((row * 8 + (c8 ^ (row & 7))) << 4);
                LDSM4(a[mt][0], a[mt][1], a[mt][2], a[mt][3], addr);
            }
            uint32_t b[8][2];
#pragma unroll
            for (int g = 0; g < 4; g++) {
                int row = wn + g * 16 + (lane & 7) + ((lane & 16) >> 1);
                int c8 = ks * 2 + ((lane >> 3) & 1);
                uint32_t addr = bOff + (uint32_t)((row * 8 + (c8 ^ (row & 7))) << 4);
                LDSM4(b[2 * g][0], b[2 * g][1], b[2 * g + 1][0], b[2 * g + 1][1], addr);
            }
#pragma unroll
            for (int mt = 0; mt < 2; mt++)
#pragma unroll
                for (int nt = 0; nt < 8; nt++)
                    MMA_F16(acc[mt][nt], a[mt], b[nt]);
        }
        __syncthreads();
        if (++s >= NSTAGE) s = 0;
    }

#pragma unroll
    for (int mt = 0; mt < 2; mt++) {
        int row0 = bm + wm + mt * 16 + (lane >> 2);
#pragma unroll
        for (int nt = 0; nt < 8; nt++) {
            int col = bn + wn + nt * 8 + (lane & 3) * 2;
            float v0 = acc[mt][nt][0] * alpha, v1 = acc[mt][nt][1] * alpha;
            float v2 = acc[mt][nt][2] * alpha, v3 = acc[mt][nt][3] * alpha;
            if (bias) {
                float b0 = bias[col], b1 = bias[col + 1];
                v0 += b0; v1 += b1; v2 += b0; v3 += b1;
            }
            OT* p0 = C + (size_t)row0 * CH + col;
            OT* p1 = C + (size_t)(row0 + 8) * CH + col;
            if (sizeof(OT) == 2) {
                *(__half2*)p0 = __floats2half2_rn(v0, v1);
                *(__half2*)p1 = __floats2half2_rn(v2, v3);
            } else {
                *(float2*)p0 = make_float2(v0, v1);
                *(float2*)p1 = make_float2(v2, v3);
            }
        }
    }
}

// ---------------------------------------------------------------------------
// Tensor-core attention: one block (128 thr, 4 warps) per (b, h).
// QK^T and PV via m16n8k16; softmax in registers (quad shfl).
// Q pre-scaled by 1/sqrt(hd) in its GEMM epilogue.
// ---------------------------------------------------------------------------
__global__ __launch_bounds__(128) void attn_kernel(
    const __half* __restrict__ Q, const __half* __restrict__ K,
    const __half* __restrict__ V, const __half* __restrict__ B64,
    __half* __restrict__ CTX)
{
    __shared__ __align__(16) __half qs[64 * 64];    // [tok], 8-unit rows, swizzled
    __shared__ __align__(16) __half ksm[64 * 64];
    __shared__ __align__(16) __half vt[32 * 64];    // [d][tok], swizzled
    __shared__ __align__(16) __half sb[64 * 72];    // bias, padded rows

    const int tid = threadIdx.x;
    const int lane = tid & 31, w = tid >> 5;
    const int b = blockIdx.x >> 4, h = blockIdx.x & 15;
    const size_t base = (size_t)b * SEQ * CH + h * HDIM;

    // Load Q, K (swizzled), V (transposed), bias slice
    {
        int tok = tid >> 1;
        int u0 = (tid & 1) * 2;           // first 8-half unit: 0 or 2
        int sw = tok & 7;
        const uint4* qsrc = (const uint4*)(Q + base + (size_t)tok * CH + u0 * 8);
        const uint4* ksrc = (const uint4*)(K + base + (size_t)tok * CH + u0 * 8);
        ((uint4*)qs)[tok * 8 + (u0 ^ sw)]       = qsrc[0];
        ((uint4*)qs)[tok * 8 + ((u0 + 1) ^ sw)] = qsrc[1];
        ((uint4*)ksm)[tok * 8 + (u0 ^ sw)]       = ksrc[0];
        ((uint4*)ksm)[tok * 8 + ((u0 + 1) ^ sw)] = ksrc[1];

        const uint4* vsrc = (const uint4*)(V + base + (size_t)tok * CH + u0 * 8);
        __half vh[16];
        *(uint4*)&vh[0] = vsrc[0];
        *(uint4*)&vh[8] = vsrc[1];
#pragma unroll
        for (int j = 0; j < 16; j++) {
            int d = u0 * 8 + j;
            vt[(d * 8 + ((tok >> 3) ^ (d & 7))) * 8 + (tok & 7)] = vh[j];
        }

        const uint4* bsrc = (const uint4*)(B64 + (size_t)h * 4096);
#pragma unroll
        for (int j = 0; j < 4; j++) {
            uint4 bv = bsrc[tid * 4 + j];
            int row = tid >> 1, col = (tid & 1) * 32 + j * 8;
            *(uint4*)&sb[row * 72 + col] = bv;
        }
    }
    __syncthreads();

    const uint32_t smq = smem_u32(qs), smk = smem_u32(ksm), smv = smem_u32(vt);

    // QK^T: warp w owns score rows 16w..16w+15
    float c[8][4];
#pragma unroll
    for (int nt = 0; nt < 8; nt++)
#pragma unroll
        for (int j = 0; j < 4; j++) c[nt][j] = 0.0f;

    uint32_t aq[2][4];
#pragma unroll
    for (int ks = 0; ks < 2; ks++) {
        int row = 16 * w + (lane & 15);
        int c8 = ks * 2 + (lane >> 4);
        uint32_t addr = smq + ((row * 8 + (c8 ^ (row & 7))) << 4);
        LDSM4(aq[ks][0], aq[ks][1], aq[ks][2], aq[ks][3], addr);
    }
#pragma unroll
    for (int g = 0; g < 4; g++) {
#pragma unroll
        for (int ks = 0; ks < 2; ks++) {
            uint32_t bk0[2], bk1[2];
            int row = 16 * g + (lane & 7) + ((lane & 16) >> 1);
            int c8 = ks * 2 + ((lane >> 3) & 1);
            uint32_t addr = smk + ((row * 8 + (c8 ^ (row & 7))) << 4);
            LDSM4(bk0[0], bk0[1], bk1[0], bk1[1], addr);
            MMA_F16(c[2 * g],     aq[ks], bk0);
            MMA_F16(c[2 * g + 1], aq[ks], bk1);
        }
    }

    // Bias add
    const int r0 = 16 * w + (lane >> 2);
#pragma unroll
    for (int nt = 0; nt < 8; nt++) {
        int col = nt * 8 + (lane & 3) * 2;
        float2 f0 = __half22float2(*(__half2*)&sb[r0 * 72 + col]);
        float2 f1 = __half22float2(*(__half2*)&sb[(r0 + 8) * 72 + col]);
        c[nt][0] += f0.x; c[nt][1] += f0.y;
        c[nt][2] += f1.x; c[nt][3] += f1.y;
    }

    // Softmax over rows r0 and r0+8 (each row spread over a quad of lanes)
    float mx0 = -1e30f, mx1 = -1e30f;
#pragma unroll
    for (int nt = 0; nt < 8; nt++) {
        mx0 = fmaxf(mx0, fmaxf(c[nt][0], c[nt][1]));
        mx1 = fmaxf(mx1, fmaxf(c[nt][2], c[nt][3]));
    }
    mx0 = fmaxf(mx0, __shfl_xor_sync(0xffffffffu, mx0, 1));
    mx0 = fmaxf(mx0, __shfl_xor_sync(0xffffffffu, mx0, 2));
    mx1 = fmaxf(mx1, __shfl_xor_sync(0xffffffffu, mx1, 1));
    mx1 = fmaxf(mx1, __shfl_xor_sync(0xffffffffu, mx1, 2));

    float sum0 = 0.0f, sum1 = 0.0f;
#pragma unroll
    for (int nt = 0; nt < 8; nt++) {
        c[nt][0] = __expf(c[nt][0] - mx0); sum0 += c[nt][0];
        c[nt][1] = __expf(c[nt][1] - mx0); sum0 += c[nt][1];
        c[nt][2] = __expf(c[nt][2] - mx1); sum1 += c[nt][2];
        c[nt][3] = __expf(c[nt][3] - mx1); sum1 += c[nt][3];
    }
    sum0 += __shfl_xor_sync(0xffffffffu, sum0, 1);
    sum0 += __shfl_xor_sync(0xffffffffu, sum0, 2);
    sum1 += __shfl_xor_sync(0xffffffffu, sum1, 1);
    sum1 += __shfl_xor_sync(0xffffffffu, sum1, 2);
    float inv0 = 1.0f / sum0, inv1 = 1.0f / sum1;

    // Convert P to A-frags for PV (c-frag -> a-frag identity)
    uint32_t ap[4][4];
#pragma unroll
    for (int ks = 0; ks < 4; ks++) {
        __half2 t0 = __floats2half2_rn(c[2 * ks][0] * inv0, c[2 * ks][1] * inv0);
        __half2 t1 = __floats2half2_rn(c[2 * ks][2] * inv1, c[2 * ks][3] * inv1);
        __half2 t2 = __floats2half2_rn(c[2 * ks + 1][0] * inv0, c[2 * ks + 1][1] * inv0);
        __half2 t3 = __floats2half2_rn(c[2 * ks + 1][2] * inv1, c[2 * ks + 1][3] * inv1);
        ap[ks][0] = *(uint32_t*)&t0;
        ap[ks][1] = *(uint32_t*)&t1;
        ap[ks][2] = *(uint32_t*)&t2;
        ap[ks][3] = *(uint32_t*)&t3;
    }

    // PV: output 16x32 per warp
    float o[4][4];
#pragma unroll
    for (int nt = 0; nt < 4; nt++)
#pragma unroll
        for (int j = 0; j < 4; j++) o[nt][j] = 0.0f;
#pragma unroll
    for (int g = 0; g < 2; g++) {
#pragma unroll
        for (int ks = 0; ks < 4; ks++) {
            uint32_t bv0[2], bv1[2];
            int row = 16 * g + (lane & 7) + ((lane & 16) >> 1);
            int c8 = ks * 2 + ((lane >> 3) & 1);
            uint32_t addr = smv + ((row * 8 + (c8 ^ (row & 7))) << 4);
            LDSM4(bv0[0], bv0[1], bv1[0], bv1[1], addr);
            MMA_F16(o[2 * g],     ap[ks], bv0);
            MMA_F16(o[2 * g + 1], ap[ks], bv1);
        }
    }

    // Write CTX (half)
#pragma unroll
    for (int nt = 0; nt < 4; nt++) {
        int col = nt * 8 + (lane & 3) * 2;
        *(__half2*)(CTX + base + (size_t)r0 * CH + col) =
            __floats2half2_rn(o[nt][0], o[nt][1]);
        *(__half2*)(CTX + base + (size_t)(r0 + 8) * CH + col) =
            __floats2half2_rn(o[nt][2], o[nt][3]);
    }
}

// ---------------------------------------------------------------------------
// Launch
// ---------------------------------------------------------------------------
extern "C" void kernel_launch(void* const* d_in, const int* in_sizes, int n_in,
                              void* d_out, int out_size) {
    const float* x          = (const float*)d_in[0];
    const float* Wq         = (const float*)d_in[1];
    const float* Wk_base    = (const float*)d_in[2];
    const float* Wk_spline  = (const float*)d_in[3];
    const float* Wv         = (const float*)d_in[4];
    const float* Wproj      = (const float*)d_in[5];
    const float* bproj      = (const float*)d_in[6];
    const float* bias_table = (const float*)d_in[7];
    float* out = (float*)d_out;

    __half *XA, *XR, *Qp, *Kp, *Vp, *CTX, *WqT, *WvT, *WpT, *WkT, *B64;
    cudaGetSymbolAddress((void**)&XA,  g_XA);
    cudaGetSymbolAddress((void**)&XR,  g_XR);
    cudaGetSymbolAddress((void**)&Qp,  g_Q);
    cudaGetSymbolAddress((void**)&Kp,  g_K);
    cudaGetSymbolAddress((void**)&Vp,  g_V);
    cudaGetSymbolAddress((void**)&CTX, g_CTX);
    cudaGetSymbolAddress((void**)&WqT, g_WqT);
    cudaGetSymbolAddress((void**)&WvT, g_WvT);
    cudaGetSymbolAddress((void**)&WpT, g_WpT);
    cudaGetSymbolAddress((void**)&WkT, g_WkT);
    cudaGetSymbolAddress((void**)&B64, g_B64);

    cudaFuncSetAttribute(gemm_f16_kernel<__half>,
                         cudaFuncAttributeMaxDynamicSharedMemorySize, SMEM_TOT);
    cudaFuncSetAttribute(gemm_f16_kernel<float>,
                         cudaFuncAttributeMaxDynamicSharedMemorySize, SMEM_TOT);

    const float scale = 0.17677669529663687f;  // 1/sqrt(32)
    dim3 gg(CH / 128, MROWS / 128);            // (4, 256)

    // Order chosen so the ncu bounded capture lands on the K-GEMM.
    build_wkt_kernel<<<(CH * XAW + 255) / 256, 256>>>(Wk_base, Wk_spline, WkT);
    prep_kernel<<<(MROWS * CH + 255) / 256, 256>>>(x, XA, XR);
    trans512_kernel<<<(CH * CH + 255) / 256, 256>>>(Wq, WqT);

    gemm_f16_kernel<__half><<<gg, 256, SMEM_TOT>>>(XA, XAW, WkT, XAW, Kp, nullptr, 1.0f);

    trans512_kernel<<<(CH * CH + 255) / 256, 256>>>(Wv, WvT);
    trans512_kernel<<<(CH * CH + 255) / 256, 256>>>(Wproj, WpT);
    build_b64_kernel<<<(HEADS * SEQ * SEQ + 255) / 256, 256>>>(bias_table, B64);

    gemm_f16_kernel<__half><<<gg, 256, SMEM_TOT>>>(XR, CH, WqT, CH, Qp, nullptr, scale);
    gemm_f16_kernel<__half><<<gg, 256, SMEM_TOT>>>(XR, CH, WvT, CH, Vp, nullptr, 1.0f);

    attn_kernel<<<BATCH * HEADS, 128>>>(Qp, Kp, Vp, B64, CTX);

    gemm_f16_kernel<float><<<gg, 256, SMEM_TOT>>>(CTX, CH, WpT, CH, out, bproj, 1.0f);
}